// round 6
// baseline (speedup 1.0000x reference)
#include <cuda_runtime.h>
#include <math.h>

#define T_LEN 2048
#define NB    256
#define DMOD  64
#define H_OUT 720
#define NBINS 1024
#define SPAN  1024            // padded slots per block (256 thr x 4)
#define SMAX  48              // max stride = align4(min(P,cols)+2), min(P,cols)<=45
#define XLEN  1224            // >= SPAN + 4*SMAX + 8
#define HSTR  1128            // >= SPAN + 2*SMAX + 4, multiple of 4
#define CH1   8               // channel chunk

struct PMeta {
    int S, padL, inner, outer, stepO, stepI, orient;
    unsigned magic;
    float wgt;
};
__device__ PMeta g_pm[2];
__device__ float g_amp[NBINS];
__device__ float g_partial[NBINS * NB];     // [bin][batch] (transposed)
__device__ float g_wp[2][2][DMOD * 9];      // [orient][layer][ch*9+slot]
__device__ float g_y2[2][NB * T_LEN];       // per-period weighted outputs

__device__ __forceinline__ unsigned mdiv(unsigned q, unsigned M) {
    return (unsigned)(((unsigned long long)q * M) >> 32);
}

// ---------------------------------------------------------------------------
// 1) Per-batch 2048-pt complex FFT, write |X[1..1024]| transposed
// ---------------------------------------------------------------------------
__global__ void fft_kernel(const float* __restrict__ x) {
    __shared__ float2 s[T_LEN];
    int b = blockIdx.x, tid = threadIdx.x;
    const float* xb = x + (size_t)b * T_LEN;
    for (int i = tid; i < T_LEN; i += blockDim.x) {
        int rev = __brev((unsigned)i) >> 21;
        s[rev] = make_float2(xb[i], 0.f);
    }
    __syncthreads();
    for (int m = 2; m <= T_LEN; m <<= 1) {
        int half = m >> 1;
        float base = -6.283185307179586f / (float)m;
        for (int k = tid; k < T_LEN / 2; k += blockDim.x) {
            int j  = k & (half - 1);
            int i0 = ((k / half) * m) + j;
            int i1 = i0 + half;
            float sa, ca;
            __sincosf(base * (float)j, &sa, &ca);
            float2 u = s[i0], v = s[i1];
            float tr = ca * v.x - sa * v.y;
            float ti = ca * v.y + sa * v.x;
            s[i1] = make_float2(u.x - tr, u.y - ti);
            s[i0] = make_float2(u.x + tr, u.y + ti);
        }
        __syncthreads();
    }
    for (int k = 1 + tid; k <= NBINS; k += blockDim.x) {
        float2 v = s[k];
        g_partial[(size_t)(k - 1) * NB + b] = sqrtf(v.x * v.x + v.y * v.y);
    }
}

// Deterministic batch mean; contiguous float4 reads per bin
__global__ void reduce_amp_kernel() {
    int k = blockIdx.x * blockDim.x + threadIdx.x;
    if (k >= NBINS) return;
    const float4* p = (const float4*)&g_partial[(size_t)k * NB];
    float acc = 0.f;
    #pragma unroll 8
    for (int i = 0; i < NB / 4; i++) {
        float4 v = p[i];
        acc += v.x + v.y + v.z + v.w;
    }
    g_amp[k] = acc * (1.f / (float)NB);
}

// ---------------------------------------------------------------------------
// 2) prep: weight permutations (both orientations) + top-2 + per-period meta
//    Permuted slot order: groups [do=0][do=+1][do=-1], within each di=-1,0,+1
//    orient 0 (inner = p): (dp,dc) = (di,do) -> src (di+1)*3 + (do+1)
//    orient 1 (inner = c): (dp,dc) = (do,di) -> src (do+1)*3 + (di+1)
// ---------------------------------------------------------------------------
__global__ void prep_kernel(const float* __restrict__ w1,
                            const float* __restrict__ w2) {
    __shared__ float sv[NBINS];
    __shared__ int   si[NBINS];
    __shared__ float b_v; __shared__ int b_i;
    int tid = threadIdx.x;   // 1024

    for (int idx = tid; idx < 2 * 2 * DMOD * 9; idx += 1024) {
        int orient = idx / (2 * DMOD * 9);
        int rem    = idx - orient * 2 * DMOD * 9;
        int layer  = rem / (DMOD * 9);
        int i      = rem - layer * DMOD * 9;
        int ch = i / 9, s = i - ch * 9;
        int g = s / 3, di = s % 3 - 1;
        int do_ = (g == 0) ? 0 : (g == 1 ? 1 : -1);
        int src = orient ? (ch * 9 + (do_ + 1) * 3 + (di + 1))
                         : (ch * 9 + (di + 1) * 3 + (do_ + 1));
        g_wp[orient][layer][i] = layer ? w2[src] : w1[src];
    }

    sv[tid] = g_amp[tid]; si[tid] = tid;
    __syncthreads();
    for (int s = NBINS / 2; s > 0; s >>= 1) {
        if (tid < s) {
            float v2 = sv[tid + s]; int i2 = si[tid + s];
            if (v2 > sv[tid] || (v2 == sv[tid] && i2 < si[tid])) { sv[tid] = v2; si[tid] = i2; }
        }
        __syncthreads();
    }
    if (tid == 0) { b_v = sv[0]; b_i = si[0]; }
    __syncthreads();
    float v1 = b_v; int i1 = b_i;
    __syncthreads();

    sv[tid] = (tid == i1) ? -1e30f : g_amp[tid]; si[tid] = tid;
    __syncthreads();
    for (int s = NBINS / 2; s > 0; s >>= 1) {
        if (tid < s) {
            float v2 = sv[tid + s]; int i2 = si[tid + s];
            if (v2 > sv[tid] || (v2 == sv[tid] && i2 < si[tid])) { sv[tid] = v2; si[tid] = i2; }
        }
        __syncthreads();
    }
    if (tid == 0) {
        float v2 = sv[0]; int i2 = si[0];
        float e2 = __expf(v2 - v1);
        float inv = 1.f / (1.f + e2);
        float wgts[2] = { inv, e2 * inv };
        int   idxs[2] = { i1, i2 };
        for (int t = 0; t < 2; t++) {
            int f = idxs[t] + 1;
            int P = (int)llrint((double)T_LEN / (double)f); if (P < 1) P = 1;
            int cols = (T_LEN + P - 1) / P;
            int orient = (P <= cols) ? 0 : 1;
            int inner = orient ? cols : P;
            int outer = orient ? P : cols;
            int S = (inner + 2 + 3) & ~3;
            PMeta pm;
            pm.S = S; pm.padL = outer * S;
            pm.inner = inner; pm.outer = outer;
            pm.stepO = orient ? 1 : P;
            pm.stepI = orient ? P : 1;
            pm.orient = orient;
            pm.magic = 0xFFFFFFFFu / (unsigned)S + 1u;
            pm.wgt = wgts[t];
            g_pm[t] = pm;
        }
    }
}

__device__ __forceinline__ float gelu_fast(float v) {
    float v2 = v * v;
    float u  = v * fmaf(0.035677408136f, v2, 0.7978845608f);
    float t;
    asm("tanh.approx.f32 %0, %1;" : "=f"(t) : "f"(u));
    return v * fmaf(0.5f, t, 0.5f);
}

// ---------------------------------------------------------------------------
// 3) Unified guard-padded fused conv1 -> GELU -> conv2 (any P)
//    Linear padded space: slot q -> o = q/S, i = q%S - 1; valid iff 0<=i<inner.
//    Guards hold zeros; 3x3 conv = 9-tap stencil at offsets do*S + di.
// ---------------------------------------------------------------------------
__global__ __launch_bounds__(256) void conv_kernel(
        const float* __restrict__ x,
        const float* __restrict__ b1,
        const float* __restrict__ b2) {
    const int period = blockIdx.z;
    const PMeta pm = g_pm[period];
    const int S = pm.S, inner = pm.inner, padL = pm.padL;
    const int stepO = pm.stepO, stepI = pm.stepI;
    const unsigned M = pm.magic;

    const int q0 = blockIdx.x * SPAN;
    if (q0 >= padL) return;
    const int b   = blockIdx.y;
    const int tid = threadIdx.x;

    __shared__ float xs[XLEN];
    __shared__ __align__(16) float w1p[DMOD][12];
    __shared__ __align__(16) float w2p[DMOD][12];
    __shared__ float b1s[DMOD];
    __shared__ float b2s_s;
    extern __shared__ float hs[];          // [CH1][HSTR]

    const float* w1g = g_wp[pm.orient][0];
    const float* w2g = g_wp[pm.orient][1];
    for (int i = tid; i < DMOD * 9; i += 256) {
        int ch = i / 9, j = i - ch * 9;
        w1p[ch][j] = w1g[i];
        w2p[ch][j] = w2g[i];
    }
    for (int i = tid; i < DMOD * 3; i += 256) {
        int ch = i / 3, j = 9 + (i - ch * 3);
        w1p[ch][j] = 0.f; w2p[ch][j] = 0.f;
    }
    if (tid < DMOD) b1s[tid] = b1[tid];
    if (tid == 0)   b2s_s = b2[0];

    // stage x over [qx0, qx0 + xlen)
    const int qx0  = q0 - 2 * S - 2;
    const int xlen = SPAN + 4 * S + 8;
    const float* xb = x + (size_t)b * T_LEN;
    for (int ii = tid; ii < xlen; ii += 256) {
        int q = qx0 + ii;
        float v = 0.f;
        if (q >= 0 && q < padL) {
            unsigned o = mdiv((unsigned)q, M);
            int i_ = q - (int)o * S - 1;
            if (i_ >= 0 && i_ < inner) {
                int n = (int)o * stepO + i_ * stepI;
                if (n < T_LEN) v = xb[n];
            }
        }
        xs[ii] = v;
    }
    __syncthreads();

    // per-thread outputs: 4 consecutive padded slots
    const int qout = q0 + tid * 4;
    int  on[4]; bool ov[4]; bool anyv = false;
    #pragma unroll
    for (int r = 0; r < 4; r++) {
        int q = qout + r;
        ov[r] = false; on[r] = 0;
        if (q < padL) {
            unsigned o = mdiv((unsigned)q, M);
            int i_ = q - (int)o * S - 1;
            if (i_ >= 0 && i_ < inner) {
                int n = (int)o * stepO + i_ * stepI;
                if (n < T_LEN) { ov[r] = true; on[r] = n; anyv = true; }
            }
        }
    }
    float acc[4] = {b2s_s, b2s_s, b2s_s, b2s_s};

    const int hq0   = q0 - S - 1;          // padded q of hs[.][0]
    const int hlen4 = SPAN + 2 * S + 4;    // multiple of 4

    for (int c0 = 0; c0 < DMOD; c0 += CH1) {
        // ---- produce: quad of h per thread per iteration ----
        for (int j = tid * 4; j < hlen4; j += 1024) {
            // per-slot grid validity
            float msk[4];
            #pragma unroll
            for (int r = 0; r < 4; r++) {
                int q = hq0 + j + r;
                bool v = false;
                if (q >= 0 && q < padL) {
                    unsigned o = mdiv((unsigned)q, M);
                    int i_ = q - (int)o * S - 1;
                    v = (i_ >= 0 && i_ < inner);
                }
                msk[r] = v ? 1.f : 0.f;
            }
            // tap rows: base_do = j + (do+1)*S, 4-aligned; 6 values each
            float row0[6], row1[6], row2[6];
            {
                const float4* x4;
                const float2* x2;
                int base;
                base = j;            x4 = (const float4*)(xs + base); x2 = (const float2*)(xs + base + 4);
                { float4 a = *x4; float2 c = *x2; row0[0]=a.x; row0[1]=a.y; row0[2]=a.z; row0[3]=a.w; row0[4]=c.x; row0[5]=c.y; }
                base = j + S;        x4 = (const float4*)(xs + base); x2 = (const float2*)(xs + base + 4);
                { float4 a = *x4; float2 c = *x2; row1[0]=a.x; row1[1]=a.y; row1[2]=a.z; row1[3]=a.w; row1[4]=c.x; row1[5]=c.y; }
                base = j + 2 * S;    x4 = (const float4*)(xs + base); x2 = (const float2*)(xs + base + 4);
                { float4 a = *x4; float2 c = *x2; row2[0]=a.x; row2[1]=a.y; row2[2]=a.z; row2[3]=a.w; row2[4]=c.x; row2[5]=c.y; }
            }
            #pragma unroll
            for (int l = 0; l < CH1; l++) {
                int ch = c0 + l;
                const float4* wr = (const float4*)w1p[ch];
                float4 wa = wr[0], wb4 = wr[1], wc = wr[2];
                float bias = b1s[ch];
                float hv[4];
                #pragma unroll
                for (int r = 0; r < 4; r++) {
                    float a = bias;
                    a = fmaf(wa.x,  row1[r],     a);
                    a = fmaf(wa.y,  row1[r + 1], a);
                    a = fmaf(wa.z,  row1[r + 2], a);
                    a = fmaf(wa.w,  row2[r],     a);
                    a = fmaf(wb4.x, row2[r + 1], a);
                    a = fmaf(wb4.y, row2[r + 2], a);
                    a = fmaf(wb4.z, row0[r],     a);
                    a = fmaf(wb4.w, row0[r + 1], a);
                    a = fmaf(wc.x,  row0[r + 2], a);
                    hv[r] = gelu_fast(a) * msk[r];
                }
                *(float4*)(hs + l * HSTR + j) = make_float4(hv[0], hv[1], hv[2], hv[3]);
            }
        }
        __syncthreads();

        // ---- consume: conv2 partial accumulation ----
        if (anyv) {
            const int jb = tid * 4 + S + 1;   // hs index of qout
            #pragma unroll
            for (int l = 0; l < CH1; l++) {
                const float4* wr = (const float4*)w2p[c0 + l];
                float4 wa = wr[0], wb4 = wr[1], wc = wr[2];
                const float* hp = &hs[l * HSTR];
                #pragma unroll
                for (int do_ = -1; do_ <= 1; do_++) {
                    int base = jb + do_ * S - 1;      // 4-aligned
                    float4 h0 = *(const float4*)(hp + base);
                    float2 h1 = *(const float2*)(hp + base + 4);
                    float hv_[6] = {h0.x, h0.y, h0.z, h0.w, h1.x, h1.y};
                    float wm1, w0, wp1;
                    if (do_ == -1)      { wm1 = wb4.z; w0 = wb4.w; wp1 = wc.x; }
                    else if (do_ == 0)  { wm1 = wa.x;  w0 = wa.y;  wp1 = wa.z; }
                    else                { wm1 = wa.w;  w0 = wb4.x; wp1 = wb4.y; }
                    #pragma unroll
                    for (int r = 0; r < 4; r++) {
                        acc[r] = fmaf(wm1, hv_[r],     acc[r]);
                        acc[r] = fmaf(w0,  hv_[r + 1], acc[r]);
                        acc[r] = fmaf(wp1, hv_[r + 2], acc[r]);
                    }
                }
            }
        }
        __syncthreads();
    }

    float* yout = g_y2[period] + (size_t)b * T_LEN;
    #pragma unroll
    for (int r = 0; r < 4; r++)
        if (ov[r]) yout[on[r]] = pm.wgt * acc[r];
}

// ---------------------------------------------------------------------------
// 4) Head GEMM: out = (y0+y1) @ head_w^T + head_b
// ---------------------------------------------------------------------------
#define BM 32
#define BN 48
#define BK 32
__global__ __launch_bounds__(256) void head_gemm_kernel(
        const float* __restrict__ hw,
        const float* __restrict__ hb,
        float* __restrict__ out) {
    __shared__ float As[BK][BM + 1];
    __shared__ float Bs[BK][BN + 1];
    int tid = threadIdx.x;
    int m0 = blockIdx.y * BM, n0 = blockIdx.x * BN;
    int tm = (tid / 16) * 2, tn = (tid % 16) * 3;
    float acc[2][3] = {{0.f,0.f,0.f},{0.f,0.f,0.f}};

    const float* y0 = g_y2[0];
    const float* y1 = g_y2[1];

    for (int k0 = 0; k0 < T_LEN; k0 += BK) {
        for (int i = tid; i < BM * BK; i += 256) {
            int m = i / BK, k = i % BK;
            size_t off = (size_t)(m0 + m) * T_LEN + k0 + k;
            As[k][m] = y0[off] + y1[off];
        }
        for (int i = tid; i < BN * BK; i += 256) {
            int n = i / BK, k = i % BK;
            Bs[k][n] = hw[(size_t)(n0 + n) * T_LEN + k0 + k];
        }
        __syncthreads();
        #pragma unroll
        for (int k = 0; k < BK; k++) {
            float a0 = As[k][tm], a1 = As[k][tm + 1];
            float b0 = Bs[k][tn], b1 = Bs[k][tn + 1], b2v = Bs[k][tn + 2];
            acc[0][0] = fmaf(a0, b0, acc[0][0]);
            acc[0][1] = fmaf(a0, b1, acc[0][1]);
            acc[0][2] = fmaf(a0, b2v, acc[0][2]);
            acc[1][0] = fmaf(a1, b0, acc[1][0]);
            acc[1][1] = fmaf(a1, b1, acc[1][1]);
            acc[1][2] = fmaf(a1, b2v, acc[1][2]);
        }
        __syncthreads();
    }
    #pragma unroll
    for (int i = 0; i < 2; i++)
        #pragma unroll
        for (int j = 0; j < 3; j++) {
            int m = m0 + tm + i, n = n0 + tn + j;
            out[(size_t)m * H_OUT + n] = acc[i][j] + hb[n];
        }
}

// ---------------------------------------------------------------------------
extern "C" void kernel_launch(void* const* d_in, const int* in_sizes, int n_in,
                              void* d_out, int out_size) {
    const float* x  = (const float*)d_in[0];
    const float* w1 = (const float*)d_in[1];
    const float* b1 = (const float*)d_in[2];
    const float* w2 = (const float*)d_in[3];
    const float* b2 = (const float*)d_in[4];
    const float* hw = (const float*)d_in[5];
    const float* hb = (const float*)d_in[6];
    float* out = (float*)d_out;

    const int HS_BYTES = CH1 * HSTR * (int)sizeof(float);   // 36096 < 48KB default

    fft_kernel<<<NB, 256>>>(x);
    reduce_amp_kernel<<<NBINS / 256, 256>>>();
    prep_kernel<<<1, NBINS>>>(w1, w2);
    conv_kernel<<<dim3(8, NB, 2), 256, HS_BYTES>>>(x, b1, b2);
    head_gemm_kernel<<<dim3(H_OUT / BN, NB / BM), 256>>>(hw, hb, out);
}

// round 8
// speedup vs baseline: 1.1785x; 1.1785x over previous
#include <cuda_runtime.h>
#include <math.h>

#define T_LEN 2048
#define NB    256
#define DMOD  64
#define H_OUT 720
#define NBINS 1024
#define SPAN  1024            // padded slots per block (256 thr x 4)
#define SMAX  48              // max stride = align4(min(P,cols)+2), min(P,cols)<=45
#define XLEN  1224            // >= SPAN + 4*SMAX + 8
#define HSTR  1128            // >= SPAN + 2*SMAX + 4, multiple of 4
#define CH1   8               // channel chunk

struct PMeta {
    int S, padL, inner, outer, stepO, stepI, orient;
    unsigned magic;
    float wgt;
};
__device__ PMeta g_pm[2];
__device__ float g_amp[NBINS];
__device__ float g_partial[NBINS * NB];     // [bin][batch] (transposed)
__device__ float g_wp[2][2][DMOD * 9];      // [orient][layer][ch*9+slot]
__device__ float g_y2[2][NB * T_LEN];       // per-period weighted outputs

__device__ __forceinline__ unsigned mdiv(unsigned q, unsigned M) {
    return (unsigned)(((unsigned long long)q * M) >> 32);
}

// ---------------------------------------------------------------------------
// 1) Per-batch 2048-pt complex FFT, write |X[1..1024]| transposed
// ---------------------------------------------------------------------------
__global__ void fft_kernel(const float* __restrict__ x) {
    __shared__ float2 s[T_LEN];
    int b = blockIdx.x, tid = threadIdx.x;
    const float* xb = x + (size_t)b * T_LEN;
    for (int i = tid; i < T_LEN; i += blockDim.x) {
        int rev = __brev((unsigned)i) >> 21;
        s[rev] = make_float2(xb[i], 0.f);
    }
    __syncthreads();
    for (int m = 2; m <= T_LEN; m <<= 1) {
        int half = m >> 1;
        float base = -6.283185307179586f / (float)m;
        for (int k = tid; k < T_LEN / 2; k += blockDim.x) {
            int j  = k & (half - 1);
            int i0 = ((k / half) * m) + j;
            int i1 = i0 + half;
            float sa, ca;
            __sincosf(base * (float)j, &sa, &ca);
            float2 u = s[i0], v = s[i1];
            float tr = ca * v.x - sa * v.y;
            float ti = ca * v.y + sa * v.x;
            s[i1] = make_float2(u.x - tr, u.y - ti);
            s[i0] = make_float2(u.x + tr, u.y + ti);
        }
        __syncthreads();
    }
    for (int k = 1 + tid; k <= NBINS; k += blockDim.x) {
        float2 v = s[k];
        g_partial[(size_t)(k - 1) * NB + b] = sqrtf(v.x * v.x + v.y * v.y);
    }
}

__global__ void reduce_amp_kernel() {
    int k = blockIdx.x * blockDim.x + threadIdx.x;
    if (k >= NBINS) return;
    const float4* p = (const float4*)&g_partial[(size_t)k * NB];
    float acc = 0.f;
    #pragma unroll 8
    for (int i = 0; i < NB / 4; i++) {
        float4 v = p[i];
        acc += v.x + v.y + v.z + v.w;
    }
    g_amp[k] = acc * (1.f / (float)NB);
}

// ---------------------------------------------------------------------------
// 2) prep: weight permutations (both orientations) + top-2 + per-period meta
// ---------------------------------------------------------------------------
__global__ void prep_kernel(const float* __restrict__ w1,
                            const float* __restrict__ w2) {
    __shared__ float sv[NBINS];
    __shared__ int   si[NBINS];
    __shared__ float b_v; __shared__ int b_i;
    int tid = threadIdx.x;   // 1024

    for (int idx = tid; idx < 2 * 2 * DMOD * 9; idx += 1024) {
        int orient = idx / (2 * DMOD * 9);
        int rem    = idx - orient * 2 * DMOD * 9;
        int layer  = rem / (DMOD * 9);
        int i      = rem - layer * DMOD * 9;
        int ch = i / 9, s = i - ch * 9;
        int g = s / 3, di = s % 3 - 1;
        int do_ = (g == 0) ? 0 : (g == 1 ? 1 : -1);
        int src = orient ? (ch * 9 + (do_ + 1) * 3 + (di + 1))
                         : (ch * 9 + (di + 1) * 3 + (do_ + 1));
        g_wp[orient][layer][i] = layer ? w2[src] : w1[src];
    }

    sv[tid] = g_amp[tid]; si[tid] = tid;
    __syncthreads();
    for (int s = NBINS / 2; s > 0; s >>= 1) {
        if (tid < s) {
            float v2 = sv[tid + s]; int i2 = si[tid + s];
            if (v2 > sv[tid] || (v2 == sv[tid] && i2 < si[tid])) { sv[tid] = v2; si[tid] = i2; }
        }
        __syncthreads();
    }
    if (tid == 0) { b_v = sv[0]; b_i = si[0]; }
    __syncthreads();
    float v1 = b_v; int i1 = b_i;
    __syncthreads();

    sv[tid] = (tid == i1) ? -1e30f : g_amp[tid]; si[tid] = tid;
    __syncthreads();
    for (int s = NBINS / 2; s > 0; s >>= 1) {
        if (tid < s) {
            float v2 = sv[tid + s]; int i2 = si[tid + s];
            if (v2 > sv[tid] || (v2 == sv[tid] && i2 < si[tid])) { sv[tid] = v2; si[tid] = i2; }
        }
        __syncthreads();
    }
    if (tid == 0) {
        float v2 = sv[0]; int i2 = si[0];
        float e2 = __expf(v2 - v1);
        float inv = 1.f / (1.f + e2);
        float wgts[2] = { inv, e2 * inv };
        int   idxs[2] = { i1, i2 };
        for (int t = 0; t < 2; t++) {
            int f = idxs[t] + 1;
            int P = (int)llrint((double)T_LEN / (double)f); if (P < 1) P = 1;
            int cols = (T_LEN + P - 1) / P;
            int orient = (P <= cols) ? 0 : 1;
            int inner = orient ? cols : P;
            int outer = orient ? P : cols;
            int S = (inner + 2 + 3) & ~3;
            PMeta pm;
            pm.S = S; pm.padL = outer * S;
            pm.inner = inner; pm.outer = outer;
            pm.stepO = orient ? 1 : P;
            pm.stepI = orient ? P : 1;
            pm.orient = orient;
            pm.magic = 0xFFFFFFFFu / (unsigned)S + 1u;
            pm.wgt = wgts[t];
            g_pm[t] = pm;
        }
    }
}

__device__ __forceinline__ float gelu_fast(float v) {
    float v2 = v * v;
    float u  = v * fmaf(0.035677408136f, v2, 0.7978845608f);
    float t;
    asm("tanh.approx.f32 %0, %1;" : "=f"(t) : "f"(u));
    return v * fmaf(0.5f, t, 0.5f);
}

// ---------------------------------------------------------------------------
// 3) Unified guard-padded fused conv1 -> GELU -> conv2 (any P)
// ---------------------------------------------------------------------------
__global__ __launch_bounds__(256, 2) void conv_kernel(
        const float* __restrict__ x,
        const float* __restrict__ b1,
        const float* __restrict__ b2) {
    const int period = blockIdx.z;
    const PMeta pm = g_pm[period];
    const int S = pm.S, inner = pm.inner, padL = pm.padL;
    const int stepO = pm.stepO, stepI = pm.stepI;
    const unsigned M = pm.magic;

    const int q0 = blockIdx.x * SPAN;
    if (q0 >= padL) return;
    const int b   = blockIdx.y;
    const int tid = threadIdx.x;

    __shared__ float xs[XLEN];
    __shared__ float ms[HSTR];             // h-slot validity mask (0/1)
    __shared__ __align__(16) float w1p[DMOD][12];
    __shared__ __align__(16) float w2p[DMOD][12];
    __shared__ float b1s[DMOD];
    __shared__ float b2s_s;
    extern __shared__ float hs[];          // [CH1][HSTR]

    const float* w1g = g_wp[pm.orient][0];
    const float* w2g = g_wp[pm.orient][1];
    for (int i = tid; i < DMOD * 9; i += 256) {
        int ch = i / 9, j = i - ch * 9;
        w1p[ch][j] = w1g[i];
        w2p[ch][j] = w2g[i];
    }
    for (int i = tid; i < DMOD * 3; i += 256) {
        int ch = i / 3, j = 9 + (i - ch * 3);
        w1p[ch][j] = 0.f; w2p[ch][j] = 0.f;
    }
    if (tid < DMOD) b1s[tid] = b1[tid];
    if (tid == 0)   b2s_s = b2[0];

    // stage x over [qx0, qx0 + xlen)
    const int qx0  = q0 - 2 * S - 2;
    const int xlen = SPAN + 4 * S + 8;
    const float* xb = x + (size_t)b * T_LEN;
    for (int ii = tid; ii < xlen; ii += 256) {
        int q = qx0 + ii;
        float v = 0.f;
        if (q >= 0 && q < padL) {
            unsigned o = mdiv((unsigned)q, M);
            int i_ = q - (int)o * S - 1;
            if (i_ >= 0 && i_ < inner) {
                int n = (int)o * stepO + i_ * stepI;
                if (n < T_LEN) v = xb[n];
            }
        }
        xs[ii] = v;
    }

    // h-slot validity mask, computed ONCE
    const int hq0   = q0 - S - 1;
    const int hlen4 = SPAN + 2 * S + 4;
    for (int j = tid; j < hlen4; j += 256) {
        int q = hq0 + j;
        bool v = false;
        if (q >= 0 && q < padL) {
            unsigned o = mdiv((unsigned)q, M);
            int i_ = q - (int)o * S - 1;
            v = (i_ >= 0 && i_ < inner);
        }
        ms[j] = v ? 1.f : 0.f;
    }
    __syncthreads();

    // per-thread outputs: 4 consecutive padded slots
    const int qout = q0 + tid * 4;
    int  on[4]; bool ov[4]; bool anyv = false;
    #pragma unroll
    for (int r = 0; r < 4; r++) {
        int q = qout + r;
        ov[r] = false; on[r] = 0;
        if (q < padL) {
            unsigned o = mdiv((unsigned)q, M);
            int i_ = q - (int)o * S - 1;
            if (i_ >= 0 && i_ < inner) {
                int n = (int)o * stepO + i_ * stepI;
                if (n < T_LEN) { ov[r] = true; on[r] = n; anyv = true; }
            }
        }
    }
    float acc[4] = {b2s_s, b2s_s, b2s_s, b2s_s};

    for (int c0 = 0; c0 < DMOD; c0 += CH1) {
        // ---- produce: quad of h per thread per iteration ----
        for (int j = tid * 4; j < hlen4; j += 1024) {
            float4 mq = *(const float4*)(ms + j);
            float row0[6], row1[6], row2[6];
            {
                float4 a; float2 c;
                a = *(const float4*)(xs + j);          c = *(const float2*)(xs + j + 4);
                row0[0]=a.x; row0[1]=a.y; row0[2]=a.z; row0[3]=a.w; row0[4]=c.x; row0[5]=c.y;
                a = *(const float4*)(xs + j + S);      c = *(const float2*)(xs + j + S + 4);
                row1[0]=a.x; row1[1]=a.y; row1[2]=a.z; row1[3]=a.w; row1[4]=c.x; row1[5]=c.y;
                a = *(const float4*)(xs + j + 2 * S);  c = *(const float2*)(xs + j + 2 * S + 4);
                row2[0]=a.x; row2[1]=a.y; row2[2]=a.z; row2[3]=a.w; row2[4]=c.x; row2[5]=c.y;
            }
            float mv[4] = {mq.x, mq.y, mq.z, mq.w};
            #pragma unroll 4
            for (int l = 0; l < CH1; l++) {
                int ch = c0 + l;
                const float4* wr = (const float4*)w1p[ch];
                float4 wa = wr[0], wb4 = wr[1], wc = wr[2];
                float bias = b1s[ch];
                float hv[4];
                #pragma unroll
                for (int r = 0; r < 4; r++) {
                    float a = bias;
                    a = fmaf(wa.x,  row1[r],     a);
                    a = fmaf(wa.y,  row1[r + 1], a);
                    a = fmaf(wa.z,  row1[r + 2], a);
                    a = fmaf(wa.w,  row2[r],     a);
                    a = fmaf(wb4.x, row2[r + 1], a);
                    a = fmaf(wb4.y, row2[r + 2], a);
                    a = fmaf(wb4.z, row0[r],     a);
                    a = fmaf(wb4.w, row0[r + 1], a);
                    a = fmaf(wc.x,  row0[r + 2], a);
                    hv[r] = gelu_fast(a) * mv[r];
                }
                *(float4*)(hs + l * HSTR + j) = make_float4(hv[0], hv[1], hv[2], hv[3]);
            }
        }
        __syncthreads();

        // ---- consume: conv2 partial accumulation ----
        if (anyv) {
            const int jb = tid * 4 + S + 1;   // hs index of qout
            #pragma unroll 4
            for (int l = 0; l < CH1; l++) {
                const float4* wr = (const float4*)w2p[c0 + l];
                float4 wa = wr[0], wb4 = wr[1], wc = wr[2];
                const float* hp = &hs[l * HSTR];
                #pragma unroll
                for (int do_ = -1; do_ <= 1; do_++) {
                    int base = jb + do_ * S - 1;      // 4-aligned
                    float4 h0 = *(const float4*)(hp + base);
                    float2 h1 = *(const float2*)(hp + base + 4);
                    float hv_[6] = {h0.x, h0.y, h0.z, h0.w, h1.x, h1.y};
                    float wm1, w0, wp1;
                    if (do_ == -1)      { wm1 = wb4.z; w0 = wb4.w; wp1 = wc.x; }
                    else if (do_ == 0)  { wm1 = wa.x;  w0 = wa.y;  wp1 = wa.z; }
                    else                { wm1 = wa.w;  w0 = wb4.x; wp1 = wb4.y; }
                    #pragma unroll
                    for (int r = 0; r < 4; r++) {
                        acc[r] = fmaf(wm1, hv_[r],     acc[r]);
                        acc[r] = fmaf(w0,  hv_[r + 1], acc[r]);
                        acc[r] = fmaf(wp1, hv_[r + 2], acc[r]);
                    }
                }
            }
        }
        __syncthreads();
    }

    float* yout = g_y2[period] + (size_t)b * T_LEN;
    #pragma unroll
    for (int r = 0; r < 4; r++)
        if (ov[r]) yout[on[r]] = pm.wgt * acc[r];
}

// ---------------------------------------------------------------------------
// 4) Head GEMM: out = (y0+y1) @ head_w^T + head_b
// ---------------------------------------------------------------------------
#define BM 32
#define BN 48
#define BK 32
__global__ __launch_bounds__(256) void head_gemm_kernel(
        const float* __restrict__ hw,
        const float* __restrict__ hb,
        float* __restrict__ out) {
    __shared__ float As[BK][BM + 1];
    __shared__ float Bs[BK][BN + 1];
    int tid = threadIdx.x;
    int m0 = blockIdx.y * BM, n0 = blockIdx.x * BN;
    int tm = (tid / 16) * 2, tn = (tid % 16) * 3;
    float acc[2][3] = {{0.f,0.f,0.f},{0.f,0.f,0.f}};

    const float* y0 = g_y2[0];
    const float* y1 = g_y2[1];

    for (int k0 = 0; k0 < T_LEN; k0 += BK) {
        for (int i = tid; i < BM * BK; i += 256) {
            int m = i / BK, k = i % BK;
            size_t off = (size_t)(m0 + m) * T_LEN + k0 + k;
            As[k][m] = y0[off] + y1[off];
        }
        for (int i = tid; i < BN * BK; i += 256) {
            int n = i / BK, k = i % BK;
            Bs[k][n] = hw[(size_t)(n0 + n) * T_LEN + k0 + k];
        }
        __syncthreads();
        #pragma unroll
        for (int k = 0; k < BK; k++) {
            float a0 = As[k][tm], a1 = As[k][tm + 1];
            float b0 = Bs[k][tn], b1 = Bs[k][tn + 1], b2v = Bs[k][tn + 2];
            acc[0][0] = fmaf(a0, b0, acc[0][0]);
            acc[0][1] = fmaf(a0, b1, acc[0][1]);
            acc[0][2] = fmaf(a0, b2v, acc[0][2]);
            acc[1][0] = fmaf(a1, b0, acc[1][0]);
            acc[1][1] = fmaf(a1, b1, acc[1][1]);
            acc[1][2] = fmaf(a1, b2v, acc[1][2]);
        }
        __syncthreads();
    }
    #pragma unroll
    for (int i = 0; i < 2; i++)
        #pragma unroll
        for (int j = 0; j < 3; j++) {
            int m = m0 + tm + i, n = n0 + tn + j;
            out[(size_t)m * H_OUT + n] = acc[i][j] + hb[n];
        }
}

// ---------------------------------------------------------------------------
extern "C" void kernel_launch(void* const* d_in, const int* in_sizes, int n_in,
                              void* d_out, int out_size) {
    const float* x  = (const float*)d_in[0];
    const float* w1 = (const float*)d_in[1];
    const float* b1 = (const float*)d_in[2];
    const float* w2 = (const float*)d_in[3];
    const float* b2 = (const float*)d_in[4];
    const float* hw = (const float*)d_in[5];
    const float* hb = (const float*)d_in[6];
    float* out = (float*)d_out;

    const int HS_BYTES = CH1 * HSTR * (int)sizeof(float);   // 36096

    // Opt-in: static (~15.8KB) + dynamic (36KB) exceeds the default 48KB
    // combined limit, so the dynamic-smem attribute must be raised.
    static int smem_set = 0;
    if (!smem_set) {
        cudaFuncSetAttribute(conv_kernel,
                             cudaFuncAttributeMaxDynamicSharedMemorySize, HS_BYTES);
        smem_set = 1;
    }

    fft_kernel<<<NB, 256>>>(x);
    reduce_amp_kernel<<<NBINS / 256, 256>>>();
    prep_kernel<<<1, NBINS>>>(w1, w2);
    conv_kernel<<<dim3(8, NB, 2), 256, HS_BYTES>>>(x, b1, b2);
    head_gemm_kernel<<<dim3(H_OUT / BN, NB / BM), 256>>>(hw, hb, out);
}

// round 9
// speedup vs baseline: 1.4803x; 1.2561x over previous
#include <cuda_runtime.h>
#include <math.h>

#define T_LEN 2048
#define NB    256
#define DMOD  64
#define H_OUT 720
#define NBINS 1024
#define SPAN  1024            // padded slots per block (256 thr x 4)
#define XLEN  1224            // >= SPAN + 4*SMAX + 8
#define HSTR  1128            // >= SPAN + 2*SMAX + 4, multiple of 4
#define CH1   4               // channel chunk
#define KSPLIT 4
#define KSEG  (T_LEN / KSPLIT)

struct PMeta {
    int S, padL, inner, outer, stepO, stepI, orient;
    unsigned magic;
    float wgt;
};
__device__ PMeta g_pm[2];
__device__ float g_amp[NBINS];
__device__ float g_partial[NBINS * NB];     // [bin][batch] (transposed)
__device__ float g_wp[2][2][DMOD * 9];      // [orient][layer][ch*9+slot]
__device__ float g_y2[2][NB * T_LEN];       // per-period weighted outputs
__device__ float g_hp[KSPLIT][NB * H_OUT];  // head GEMM split-K partials

__device__ __forceinline__ unsigned mdiv(unsigned q, unsigned M) {
    return (unsigned)(((unsigned long long)q * M) >> 32);
}

// ---------------------------------------------------------------------------
// 1) Per-batch 2048-pt complex FFT (twiddle table), write |X[1..1024]|
// ---------------------------------------------------------------------------
__global__ void fft_kernel(const float* __restrict__ x) {
    __shared__ float2 s[T_LEN];
    __shared__ float2 tw[T_LEN / 2];
    int b = blockIdx.x, tid = threadIdx.x;
    const float* xb = x + (size_t)b * T_LEN;
    for (int i = tid; i < T_LEN; i += blockDim.x) {
        int rev = __brev((unsigned)i) >> 21;   // 11-bit reverse
        s[rev] = make_float2(xb[i], 0.f);
    }
    const float base = -6.283185307179586f / (float)T_LEN;
    for (int k = tid; k < T_LEN / 2; k += blockDim.x) {
        float sa, ca;
        __sincosf(base * (float)k, &sa, &ca);
        tw[k] = make_float2(ca, sa);
    }
    __syncthreads();
    for (int m = 2; m <= T_LEN; m <<= 1) {
        int half = m >> 1;
        int step = T_LEN / m;
        for (int k = tid; k < T_LEN / 2; k += blockDim.x) {
            int j  = k & (half - 1);
            int i0 = ((k / half) * m) + j;
            int i1 = i0 + half;
            float2 w = tw[j * step];
            float2 u = s[i0], v = s[i1];
            float tr = w.x * v.x - w.y * v.y;
            float ti = w.x * v.y + w.y * v.x;
            s[i1] = make_float2(u.x - tr, u.y - ti);
            s[i0] = make_float2(u.x + tr, u.y + ti);
        }
        __syncthreads();
    }
    for (int k = 1 + tid; k <= NBINS; k += blockDim.x) {
        float2 v = s[k];
        g_partial[(size_t)(k - 1) * NB + b] = sqrtf(v.x * v.x + v.y * v.y);
    }
}

__global__ void reduce_amp_kernel() {
    int k = blockIdx.x * blockDim.x + threadIdx.x;
    if (k >= NBINS) return;
    const float4* p = (const float4*)&g_partial[(size_t)k * NB];
    float acc = 0.f;
    #pragma unroll 8
    for (int i = 0; i < NB / 4; i++) {
        float4 v = p[i];
        acc += v.x + v.y + v.z + v.w;
    }
    g_amp[k] = acc * (1.f / (float)NB);
}

// ---------------------------------------------------------------------------
// 2) prep: weight permutations (both orientations) + top-2 + per-period meta
// ---------------------------------------------------------------------------
__global__ void prep_kernel(const float* __restrict__ w1,
                            const float* __restrict__ w2) {
    __shared__ float sv[NBINS];
    __shared__ int   si[NBINS];
    __shared__ float b_v; __shared__ int b_i;
    int tid = threadIdx.x;   // 1024

    for (int idx = tid; idx < 2 * 2 * DMOD * 9; idx += 1024) {
        int orient = idx / (2 * DMOD * 9);
        int rem    = idx - orient * 2 * DMOD * 9;
        int layer  = rem / (DMOD * 9);
        int i      = rem - layer * DMOD * 9;
        int ch = i / 9, s = i - ch * 9;
        int g = s / 3, di = s % 3 - 1;
        int do_ = (g == 0) ? 0 : (g == 1 ? 1 : -1);
        int src = orient ? (ch * 9 + (do_ + 1) * 3 + (di + 1))
                         : (ch * 9 + (di + 1) * 3 + (do_ + 1));
        g_wp[orient][layer][i] = layer ? w2[src] : w1[src];
    }

    sv[tid] = g_amp[tid]; si[tid] = tid;
    __syncthreads();
    for (int s = NBINS / 2; s > 0; s >>= 1) {
        if (tid < s) {
            float v2 = sv[tid + s]; int i2 = si[tid + s];
            if (v2 > sv[tid] || (v2 == sv[tid] && i2 < si[tid])) { sv[tid] = v2; si[tid] = i2; }
        }
        __syncthreads();
    }
    if (tid == 0) { b_v = sv[0]; b_i = si[0]; }
    __syncthreads();
    float v1 = b_v; int i1 = b_i;
    __syncthreads();

    sv[tid] = (tid == i1) ? -1e30f : g_amp[tid]; si[tid] = tid;
    __syncthreads();
    for (int s = NBINS / 2; s > 0; s >>= 1) {
        if (tid < s) {
            float v2 = sv[tid + s]; int i2 = si[tid + s];
            if (v2 > sv[tid] || (v2 == sv[tid] && i2 < si[tid])) { sv[tid] = v2; si[tid] = i2; }
        }
        __syncthreads();
    }
    if (tid == 0) {
        float v2 = sv[0]; int i2 = si[0];
        float e2 = __expf(v2 - v1);
        float inv = 1.f / (1.f + e2);
        float wgts[2] = { inv, e2 * inv };
        int   idxs[2] = { i1, i2 };
        for (int t = 0; t < 2; t++) {
            int f = idxs[t] + 1;
            int P = (int)llrint((double)T_LEN / (double)f); if (P < 1) P = 1;
            int cols = (T_LEN + P - 1) / P;
            int orient = (P <= cols) ? 0 : 1;
            int inner = orient ? cols : P;
            int outer = orient ? P : cols;
            int S = (inner + 2 + 3) & ~3;
            PMeta pm;
            pm.S = S; pm.padL = outer * S;
            pm.inner = inner; pm.outer = outer;
            pm.stepO = orient ? 1 : P;
            pm.stepI = orient ? P : 1;
            pm.orient = orient;
            pm.magic = 0xFFFFFFFFu / (unsigned)S + 1u;
            pm.wgt = wgts[t];
            g_pm[t] = pm;
        }
    }
}

__device__ __forceinline__ float gelu_fast(float v) {
    float v2 = v * v;
    float u  = v * fmaf(0.035677408136f, v2, 0.7978845608f);
    float t;
    asm("tanh.approx.f32 %0, %1;" : "=f"(t) : "f"(u));
    return v * fmaf(0.5f, t, 0.5f);
}

// ---------------------------------------------------------------------------
// 3) Unified guard-padded fused conv1 -> GELU -> conv2 (any P)
// ---------------------------------------------------------------------------
__global__ __launch_bounds__(256, 3) void conv_kernel(
        const float* __restrict__ x,
        const float* __restrict__ b1,
        const float* __restrict__ b2) {
    const int period = blockIdx.z;
    const PMeta pm = g_pm[period];
    const int S = pm.S, inner = pm.inner, padL = pm.padL;
    const int stepO = pm.stepO, stepI = pm.stepI;
    const unsigned M = pm.magic;

    const int q0 = blockIdx.x * SPAN;
    if (q0 >= padL) return;
    const int b   = blockIdx.y;
    const int tid = threadIdx.x;

    __shared__ float xs[XLEN];
    __shared__ float ms[HSTR];             // h-slot validity mask (0/1)
    __shared__ __align__(16) float w1p[DMOD][12];
    __shared__ __align__(16) float w2p[DMOD][12];
    __shared__ float b1s[DMOD];
    __shared__ float b2s_s;
    extern __shared__ float hs[];          // [CH1][HSTR]

    const float* w1g = g_wp[pm.orient][0];
    const float* w2g = g_wp[pm.orient][1];
    for (int i = tid; i < DMOD * 9; i += 256) {
        int ch = i / 9, j = i - ch * 9;
        w1p[ch][j] = w1g[i];
        w2p[ch][j] = w2g[i];
    }
    for (int i = tid; i < DMOD * 3; i += 256) {
        int ch = i / 3, j = 9 + (i - ch * 3);
        w1p[ch][j] = 0.f; w2p[ch][j] = 0.f;
    }
    if (tid < DMOD) b1s[tid] = b1[tid];
    if (tid == 0)   b2s_s = b2[0];

    // stage x over [qx0, qx0 + xlen)
    const int qx0  = q0 - 2 * S - 2;
    const int xlen = SPAN + 4 * S + 8;
    const float* xb = x + (size_t)b * T_LEN;
    for (int ii = tid; ii < xlen; ii += 256) {
        int q = qx0 + ii;
        float v = 0.f;
        if (q >= 0 && q < padL) {
            unsigned o = mdiv((unsigned)q, M);
            int i_ = q - (int)o * S - 1;
            if (i_ >= 0 && i_ < inner) {
                int n = (int)o * stepO + i_ * stepI;
                if (n < T_LEN) v = xb[n];
            }
        }
        xs[ii] = v;
    }

    // h-slot validity mask, computed ONCE
    const int hq0   = q0 - S - 1;
    const int hlen4 = SPAN + 2 * S + 4;
    for (int j = tid; j < hlen4; j += 256) {
        int q = hq0 + j;
        bool v = false;
        if (q >= 0 && q < padL) {
            unsigned o = mdiv((unsigned)q, M);
            int i_ = q - (int)o * S - 1;
            v = (i_ >= 0 && i_ < inner);
        }
        ms[j] = v ? 1.f : 0.f;
    }
    __syncthreads();

    // per-thread outputs: 4 consecutive padded slots
    const int qout = q0 + tid * 4;
    int  on[4]; bool ov[4]; bool anyv = false;
    #pragma unroll
    for (int r = 0; r < 4; r++) {
        int q = qout + r;
        ov[r] = false; on[r] = 0;
        if (q < padL) {
            unsigned o = mdiv((unsigned)q, M);
            int i_ = q - (int)o * S - 1;
            if (i_ >= 0 && i_ < inner) {
                int n = (int)o * stepO + i_ * stepI;
                if (n < T_LEN) { ov[r] = true; on[r] = n; anyv = true; }
            }
        }
    }
    float acc[4] = {b2s_s, b2s_s, b2s_s, b2s_s};

    for (int c0 = 0; c0 < DMOD; c0 += CH1) {
        // ---- produce: quad of h per thread per iteration ----
        for (int j = tid * 4; j < hlen4; j += 1024) {
            float4 mq = *(const float4*)(ms + j);
            float row0[6], row1[6], row2[6];
            {
                float4 a; float2 c;
                a = *(const float4*)(xs + j);          c = *(const float2*)(xs + j + 4);
                row0[0]=a.x; row0[1]=a.y; row0[2]=a.z; row0[3]=a.w; row0[4]=c.x; row0[5]=c.y;
                a = *(const float4*)(xs + j + S);      c = *(const float2*)(xs + j + S + 4);
                row1[0]=a.x; row1[1]=a.y; row1[2]=a.z; row1[3]=a.w; row1[4]=c.x; row1[5]=c.y;
                a = *(const float4*)(xs + j + 2 * S);  c = *(const float2*)(xs + j + 2 * S + 4);
                row2[0]=a.x; row2[1]=a.y; row2[2]=a.z; row2[3]=a.w; row2[4]=c.x; row2[5]=c.y;
            }
            float mv[4] = {mq.x, mq.y, mq.z, mq.w};
            #pragma unroll
            for (int l = 0; l < CH1; l++) {
                int ch = c0 + l;
                const float4* wr = (const float4*)w1p[ch];
                float4 wa = wr[0], wb4 = wr[1], wc = wr[2];
                float bias = b1s[ch];
                float hv[4];
                #pragma unroll
                for (int r = 0; r < 4; r++) {
                    float a = bias;
                    a = fmaf(wa.x,  row1[r],     a);
                    a = fmaf(wa.y,  row1[r + 1], a);
                    a = fmaf(wa.z,  row1[r + 2], a);
                    a = fmaf(wa.w,  row2[r],     a);
                    a = fmaf(wb4.x, row2[r + 1], a);
                    a = fmaf(wb4.y, row2[r + 2], a);
                    a = fmaf(wb4.z, row0[r],     a);
                    a = fmaf(wb4.w, row0[r + 1], a);
                    a = fmaf(wc.x,  row0[r + 2], a);
                    hv[r] = gelu_fast(a) * mv[r];
                }
                *(float4*)(hs + l * HSTR + j) = make_float4(hv[0], hv[1], hv[2], hv[3]);
            }
        }
        __syncthreads();

        // ---- consume: conv2 partial accumulation ----
        if (anyv) {
            const int jb = tid * 4 + S + 1;   // hs index of qout
            #pragma unroll
            for (int l = 0; l < CH1; l++) {
                const float4* wr = (const float4*)w2p[c0 + l];
                float4 wa = wr[0], wb4 = wr[1], wc = wr[2];
                const float* hp = &hs[l * HSTR];
                #pragma unroll
                for (int do_ = -1; do_ <= 1; do_++) {
                    int base = jb + do_ * S - 1;      // 4-aligned
                    float4 h0 = *(const float4*)(hp + base);
                    float2 h1 = *(const float2*)(hp + base + 4);
                    float hv_[6] = {h0.x, h0.y, h0.z, h0.w, h1.x, h1.y};
                    float wm1, w0, wp1;
                    if (do_ == -1)      { wm1 = wb4.z; w0 = wb4.w; wp1 = wc.x; }
                    else if (do_ == 0)  { wm1 = wa.x;  w0 = wa.y;  wp1 = wa.z; }
                    else                { wm1 = wa.w;  w0 = wb4.x; wp1 = wb4.y; }
                    #pragma unroll
                    for (int r = 0; r < 4; r++) {
                        acc[r] = fmaf(wm1, hv_[r],     acc[r]);
                        acc[r] = fmaf(w0,  hv_[r + 1], acc[r]);
                        acc[r] = fmaf(wp1, hv_[r + 2], acc[r]);
                    }
                }
            }
        }
        __syncthreads();
    }

    float* yout = g_y2[period] + (size_t)b * T_LEN;
    #pragma unroll
    for (int r = 0; r < 4; r++)
        if (ov[r]) yout[on[r]] = pm.wgt * acc[r];
}

// ---------------------------------------------------------------------------
// 4) Head GEMM, split-K: partial[kz] = y[:, kz*512:(kz+1)*512] @ hw^T
//    64x64 tile, 4x4 micro, float4 smem loads
// ---------------------------------------------------------------------------
#define GBM 64
#define GBN 64
#define GBK 32
__global__ __launch_bounds__(256) void head_gemm_kernel(
        const float* __restrict__ hw) {
    __shared__ __align__(16) float As[GBK][GBM];
    __shared__ __align__(16) float Bs[GBK][GBN];
    const int tid = threadIdx.x;
    const int n0 = blockIdx.x * GBN, m0 = blockIdx.y * GBM;
    const int kz = blockIdx.z;
    const int ty = tid / 16, tx = tid % 16;      // 16x16
    const int tm = ty * 4, tn = tx * 4;

    const float* y0 = g_y2[0];
    const float* y1 = g_y2[1];

    float acc[4][4];
    #pragma unroll
    for (int i = 0; i < 4; i++)
        #pragma unroll
        for (int j = 0; j < 4; j++) acc[i][j] = 0.f;

    const int kbase = kz * KSEG;
    for (int k0 = kbase; k0 < kbase + KSEG; k0 += GBK) {
        #pragma unroll
        for (int i = tid; i < GBM * GBK; i += 256) {
            int m = i / GBK, k = i % GBK;
            size_t off = (size_t)(m0 + m) * T_LEN + k0 + k;
            As[k][m] = y0[off] + y1[off];
        }
        #pragma unroll
        for (int i = tid; i < GBN * GBK; i += 256) {
            int n = i / GBK, k = i % GBK;
            Bs[k][n] = (n0 + n < H_OUT) ? hw[(size_t)(n0 + n) * T_LEN + k0 + k] : 0.f;
        }
        __syncthreads();
        #pragma unroll
        for (int k = 0; k < GBK; k++) {
            float4 a4 = *(const float4*)&As[k][tm];
            float4 b4 = *(const float4*)&Bs[k][tn];
            float av[4] = {a4.x, a4.y, a4.z, a4.w};
            float bv[4] = {b4.x, b4.y, b4.z, b4.w};
            #pragma unroll
            for (int i = 0; i < 4; i++)
                #pragma unroll
                for (int j = 0; j < 4; j++)
                    acc[i][j] = fmaf(av[i], bv[j], acc[i][j]);
        }
        __syncthreads();
    }
    float* outp = g_hp[kz];
    #pragma unroll
    for (int i = 0; i < 4; i++)
        #pragma unroll
        for (int j = 0; j < 4; j++) {
            int m = m0 + tm + i, n = n0 + tn + j;
            if (n < H_OUT) outp[(size_t)m * H_OUT + n] = acc[i][j];
        }
}

__global__ void head_epilogue_kernel(const float* __restrict__ hb,
                                     float* __restrict__ out) {
    int idx = blockIdx.x * blockDim.x + threadIdx.x;
    if (idx >= NB * H_OUT) return;
    int n = idx % H_OUT;
    float v = hb[n];
    #pragma unroll
    for (int kz = 0; kz < KSPLIT; kz++) v += g_hp[kz][idx];
    out[idx] = v;
}

// ---------------------------------------------------------------------------
extern "C" void kernel_launch(void* const* d_in, const int* in_sizes, int n_in,
                              void* d_out, int out_size) {
    const float* x  = (const float*)d_in[0];
    const float* w1 = (const float*)d_in[1];
    const float* b1 = (const float*)d_in[2];
    const float* w2 = (const float*)d_in[3];
    const float* b2 = (const float*)d_in[4];
    const float* hw = (const float*)d_in[5];
    const float* hb = (const float*)d_in[6];
    float* out = (float*)d_out;

    const int HS_BYTES = CH1 * HSTR * (int)sizeof(float);   // 18048

    // static (~16KB) + dynamic (18KB) exceeds default 48KB only marginally;
    // opt in anyway to be safe across driver versions.
    static int smem_set = 0;
    if (!smem_set) {
        cudaFuncSetAttribute(conv_kernel,
                             cudaFuncAttributeMaxDynamicSharedMemorySize, HS_BYTES);
        smem_set = 1;
    }

    fft_kernel<<<NB, 256>>>(x);
    reduce_amp_kernel<<<NBINS / 256, 256>>>();
    prep_kernel<<<1, NBINS>>>(w1, w2);
    conv_kernel<<<dim3(6, NB, 2), 256, HS_BYTES>>>(x, b1, b2);
    head_gemm_kernel<<<dim3((H_OUT + GBN - 1) / GBN, NB / GBM, KSPLIT), 256>>>(hw);
    head_epilogue_kernel<<<(NB * H_OUT + 255) / 256, 256>>>(hb, out);
}

// round 10
// speedup vs baseline: 1.6769x; 1.1328x over previous
#include <cuda_runtime.h>
#include <math.h>

#define T_LEN 2048
#define NB    256
#define DMOD  64
#define H_OUT 720
#define NBINS 1024
#define OUTSPAN 928           // outputs per block
#define USPAN  1024           // u slots per block (256 thr x 4)
#define XLEN2  1136           // x staging: USPAN + 2*48 + margin, 4-aligned
#define NCONVBLK 9            // ceil(max padL 8192 / 928)
#define KSPLIT 4
#define KSEG  (T_LEN / KSPLIT)

struct PMeta {
    int S, padL, inner, outer, stepO, stepI, orient;
    unsigned magic;
    float wgt;
};
__device__ PMeta g_pm[2];
__device__ float g_amp[NBINS];
__device__ float g_partial[NBINS * NB];     // [bin][batch] (transposed)
__device__ float g_wp[2][2][DMOD * 9];      // [orient][layer][ch*9+slot]
__device__ float g_y2[2][NB * T_LEN];       // per-period weighted outputs
__device__ float g_hp[KSPLIT][NB * H_OUT];  // head GEMM split-K partials

__device__ __forceinline__ unsigned mdiv(unsigned q, unsigned M) {
    return (unsigned)(((unsigned long long)q * M) >> 32);
}

// ---------------------------------------------------------------------------
// 1) Per-batch 2048-pt complex FFT (twiddle table), write |X[1..1024]|
// ---------------------------------------------------------------------------
__global__ void fft_kernel(const float* __restrict__ x) {
    __shared__ float2 s[T_LEN];
    __shared__ float2 tw[T_LEN / 2];
    int b = blockIdx.x, tid = threadIdx.x;
    const float* xb = x + (size_t)b * T_LEN;
    for (int i = tid; i < T_LEN; i += blockDim.x) {
        int rev = __brev((unsigned)i) >> 21;   // 11-bit reverse
        s[rev] = make_float2(xb[i], 0.f);
    }
    const float base = -6.283185307179586f / (float)T_LEN;
    for (int k = tid; k < T_LEN / 2; k += blockDim.x) {
        float sa, ca;
        __sincosf(base * (float)k, &sa, &ca);
        tw[k] = make_float2(ca, sa);
    }
    __syncthreads();
    for (int m = 2; m <= T_LEN; m <<= 1) {
        int half = m >> 1;
        int step = T_LEN / m;
        for (int k = tid; k < T_LEN / 2; k += blockDim.x) {
            int j  = k & (half - 1);
            int i0 = ((k / half) * m) + j;
            int i1 = i0 + half;
            float2 w = tw[j * step];
            float2 u = s[i0], v = s[i1];
            float tr = w.x * v.x - w.y * v.y;
            float ti = w.x * v.y + w.y * v.x;
            s[i1] = make_float2(u.x - tr, u.y - ti);
            s[i0] = make_float2(u.x + tr, u.y + ti);
        }
        __syncthreads();
    }
    for (int k = 1 + tid; k <= NBINS; k += blockDim.x) {
        float2 v = s[k];
        g_partial[(size_t)(k - 1) * NB + b] = sqrtf(v.x * v.x + v.y * v.y);
    }
}

__global__ void reduce_amp_kernel() {
    int k = blockIdx.x * blockDim.x + threadIdx.x;
    if (k >= NBINS) return;
    const float4* p = (const float4*)&g_partial[(size_t)k * NB];
    float acc = 0.f;
    #pragma unroll 8
    for (int i = 0; i < NB / 4; i++) {
        float4 v = p[i];
        acc += v.x + v.y + v.z + v.w;
    }
    g_amp[k] = acc * (1.f / (float)NB);
}

// ---------------------------------------------------------------------------
// 2) prep: weight permutations (both orientations) + top-2 + per-period meta
//    Permuted slot order: groups [do=0][do=+1][do=-1], within each di=-1,0,+1
// ---------------------------------------------------------------------------
__global__ void prep_kernel(const float* __restrict__ w1,
                            const float* __restrict__ w2) {
    __shared__ float sv[NBINS];
    __shared__ int   si[NBINS];
    __shared__ float b_v; __shared__ int b_i;
    int tid = threadIdx.x;   // 1024

    for (int idx = tid; idx < 2 * 2 * DMOD * 9; idx += 1024) {
        int orient = idx / (2 * DMOD * 9);
        int rem    = idx - orient * 2 * DMOD * 9;
        int layer  = rem / (DMOD * 9);
        int i      = rem - layer * DMOD * 9;
        int ch = i / 9, s = i - ch * 9;
        int g = s / 3, di = s % 3 - 1;
        int do_ = (g == 0) ? 0 : (g == 1 ? 1 : -1);
        int src = orient ? (ch * 9 + (do_ + 1) * 3 + (di + 1))
                         : (ch * 9 + (di + 1) * 3 + (do_ + 1));
        g_wp[orient][layer][i] = layer ? w2[src] : w1[src];
    }

    sv[tid] = g_amp[tid]; si[tid] = tid;
    __syncthreads();
    for (int s = NBINS / 2; s > 0; s >>= 1) {
        if (tid < s) {
            float v2 = sv[tid + s]; int i2 = si[tid + s];
            if (v2 > sv[tid] || (v2 == sv[tid] && i2 < si[tid])) { sv[tid] = v2; si[tid] = i2; }
        }
        __syncthreads();
    }
    if (tid == 0) { b_v = sv[0]; b_i = si[0]; }
    __syncthreads();
    float v1 = b_v; int i1 = b_i;
    __syncthreads();

    sv[tid] = (tid == i1) ? -1e30f : g_amp[tid]; si[tid] = tid;
    __syncthreads();
    for (int s = NBINS / 2; s > 0; s >>= 1) {
        if (tid < s) {
            float v2 = sv[tid + s]; int i2 = si[tid + s];
            if (v2 > sv[tid] || (v2 == sv[tid] && i2 < si[tid])) { sv[tid] = v2; si[tid] = i2; }
        }
        __syncthreads();
    }
    if (tid == 0) {
        float v2 = sv[0]; int i2 = si[0];
        float e2 = __expf(v2 - v1);
        float inv = 1.f / (1.f + e2);
        float wgts[2] = { inv, e2 * inv };
        int   idxs[2] = { i1, i2 };
        for (int t = 0; t < 2; t++) {
            int f = idxs[t] + 1;
            int P = (int)llrint((double)T_LEN / (double)f); if (P < 1) P = 1;
            int cols = (T_LEN + P - 1) / P;
            int orient = (P <= cols) ? 0 : 1;
            int inner = orient ? cols : P;
            int outer = orient ? P : cols;
            int S = (inner + 2 + 3) & ~3;
            PMeta pm;
            pm.S = S; pm.padL = outer * S;
            pm.inner = inner; pm.outer = outer;
            pm.stepO = orient ? 1 : P;
            pm.stepI = orient ? P : 1;
            pm.orient = orient;
            pm.magic = 0xFFFFFFFFu / (unsigned)S + 1u;
            pm.wgt = wgts[t];
            g_pm[t] = pm;
        }
    }
}

__device__ __forceinline__ float gelu_fast(float v) {
    float v2 = v * v;
    float u  = v * fmaf(0.035677408136f, v2, 0.7978845608f);
    float t;
    asm("tanh.approx.f32 %0, %1;" : "=f"(t) : "f"(u));
    return v * fmaf(0.5f, t, 0.5f);
}

// ---------------------------------------------------------------------------
// 3) Register-resident fused conv1 -> GELU -> conv2.
//    Each thread owns 4 u-slots; x taps (3 rows x 8) live in registers across
//    the whole channel loop. Per channel: compute 6 h in registers, fold into
//    12 accumulators U0/Up/Um (row partials u_do). Cross-row exchange done
//    ONCE at the end via smem. Block covers u-span [qb, qb+1024), outputs
//    [qb+48, qb+976) -> blocks stride 928.
// ---------------------------------------------------------------------------
__global__ __launch_bounds__(256, 2) void conv_kernel(
        const float* __restrict__ x,
        const float* __restrict__ b1,
        const float* __restrict__ b2) {
    const int period = blockIdx.z;
    const PMeta pm = g_pm[period];
    const int S = pm.S, inner = pm.inner, padL = pm.padL;
    const int stepO = pm.stepO, stepI = pm.stepI;
    const unsigned M = pm.magic;

    if (blockIdx.x * OUTSPAN >= padL) return;
    const int qb  = blockIdx.x * OUTSPAN - 48;   // u-span start (4-aligned)
    const int b   = blockIdx.y;
    const int tid = threadIdx.x;

    __shared__ float xs[XLEN2];
    __shared__ float sUm[USPAN];
    __shared__ float sUp[USPAN];
    __shared__ __align__(16) float w1p[DMOD][12];
    __shared__ __align__(16) float w2p[DMOD][12];
    __shared__ float b1s[DMOD];
    __shared__ float b2s_s;

    const float* w1g = g_wp[pm.orient][0];
    const float* w2g = g_wp[pm.orient][1];
    for (int i = tid; i < DMOD * 9; i += 256) {
        int ch = i / 9, j = i - ch * 9;
        w1p[ch][j] = w1g[i];
        w2p[ch][j] = w2g[i];
    }
    if (tid < DMOD) b1s[tid] = b1[tid];
    if (tid == 0)   b2s_s = b2[0];

    // stage x over padded q in [qb - 52, qb - 52 + XLEN2)
    const float* xb = x + (size_t)b * T_LEN;
    for (int i = tid; i < XLEN2; i += 256) {
        int q = qb - 52 + i;
        float v = 0.f;
        if (q >= 0 && q < padL) {
            unsigned o = mdiv((unsigned)q, M);
            int i_ = q - (int)o * S - 1;
            if (i_ >= 0 && i_ < inner) {
                int n = (int)o * stepO + i_ * stepI;
                if (n < T_LEN) v = xb[n];
            }
        }
        xs[i] = v;
    }
    __syncthreads();

    // x taps into registers: rows do=-1,0,+1; inner offsets ju-2 .. ju+5
    float r0[8], r1[8], r2[8];
    {
        const float* xr = xs + tid * 4 + 50;     // index of (ju-2), 2-aligned
        #pragma unroll
        for (int k = 0; k < 4; k++) {
            float2 v;
            v = *(const float2*)(xr + 2 * k);       r1[2*k] = v.x; r1[2*k+1] = v.y;
            v = *(const float2*)(xr + S + 2 * k);   r2[2*k] = v.x; r2[2*k+1] = v.y;
            v = *(const float2*)(xr - S + 2 * k);   r0[2*k] = v.x; r0[2*k+1] = v.y;
        }
    }

    // h-position masks (6) and output metadata (4)
    float m[6];
    #pragma unroll
    for (int t = 0; t < 6; t++) {
        int q = qb + tid * 4 - 1 + t;
        bool v = false;
        if (q >= 0 && q < padL) {
            unsigned o = mdiv((unsigned)q, M);
            int i_ = q - (int)o * S - 1;
            v = (i_ >= 0 && i_ < inner);
        }
        m[t] = v ? 1.f : 0.f;
    }
    int on[4]; bool ov[4]; bool anyv = false;
    #pragma unroll
    for (int r = 0; r < 4; r++) {
        int lj = tid * 4 + r;
        int q  = qb + lj;
        ov[r] = false; on[r] = 0;
        if (lj >= 48 && lj < 48 + OUTSPAN && q < padL) {
            unsigned o = mdiv((unsigned)q, M);
            int i_ = q - (int)o * S - 1;
            if (i_ >= 0 && i_ < inner) {
                int n = (int)o * stepO + i_ * stepI;
                if (n < T_LEN) { ov[r] = true; on[r] = n; anyv = true; }
            }
        }
    }

    float U0[4] = {0.f, 0.f, 0.f, 0.f};
    float Up[4] = {0.f, 0.f, 0.f, 0.f};
    float Um[4] = {0.f, 0.f, 0.f, 0.f};

    #pragma unroll 2
    for (int ch = 0; ch < DMOD; ch++) {
        const float4* w1r = (const float4*)w1p[ch];
        float4 wa = w1r[0], wb = w1r[1], wc = w1r[2];
        float bias = b1s[ch];
        float h[6];
        #pragma unroll
        for (int t = 0; t < 6; t++) {
            float a = bias;
            a = fmaf(wa.x, r1[t],     a);
            a = fmaf(wa.y, r1[t + 1], a);
            a = fmaf(wa.z, r1[t + 2], a);
            a = fmaf(wa.w, r2[t],     a);
            a = fmaf(wb.x, r2[t + 1], a);
            a = fmaf(wb.y, r2[t + 2], a);
            a = fmaf(wb.z, r0[t],     a);
            a = fmaf(wb.w, r0[t + 1], a);
            a = fmaf(wc.x, r0[t + 2], a);
            h[t] = gelu_fast(a) * m[t];
        }
        const float4* w2r = (const float4*)w2p[ch];
        float4 va = w2r[0], vb = w2r[1], vc = w2r[2];
        #pragma unroll
        for (int r = 0; r < 4; r++) {
            U0[r] = fmaf(va.x, h[r],     U0[r]);
            U0[r] = fmaf(va.y, h[r + 1], U0[r]);
            U0[r] = fmaf(va.z, h[r + 2], U0[r]);
            Up[r] = fmaf(va.w, h[r],     Up[r]);
            Up[r] = fmaf(vb.x, h[r + 1], Up[r]);
            Up[r] = fmaf(vb.y, h[r + 2], Up[r]);
            Um[r] = fmaf(vb.z, h[r],     Um[r]);
            Um[r] = fmaf(vb.w, h[r + 1], Um[r]);
            Um[r] = fmaf(vc.x, h[r + 2], Um[r]);
        }
    }

    // one-time cross-row exchange
    *(float4*)(sUm + tid * 4) = make_float4(Um[0], Um[1], Um[2], Um[3]);
    *(float4*)(sUp + tid * 4) = make_float4(Up[0], Up[1], Up[2], Up[3]);
    __syncthreads();

    if (anyv) {
        float* yout = g_y2[period] + (size_t)b * T_LEN;
        #pragma unroll
        for (int r = 0; r < 4; r++) {
            if (ov[r]) {
                int lj = tid * 4 + r;
                float val = b2s_s + U0[r] + sUm[lj - S] + sUp[lj + S];
                yout[on[r]] = pm.wgt * val;
            }
        }
    }
}

// ---------------------------------------------------------------------------
// 4) Head GEMM, split-K: partial[kz] = y[:, kz*512:(kz+1)*512] @ hw^T
// ---------------------------------------------------------------------------
#define GBM 64
#define GBN 64
#define GBK 32
__global__ __launch_bounds__(256) void head_gemm_kernel(
        const float* __restrict__ hw) {
    __shared__ __align__(16) float As[GBK][GBM];
    __shared__ __align__(16) float Bs[GBK][GBN];
    const int tid = threadIdx.x;
    const int n0 = blockIdx.x * GBN, m0 = blockIdx.y * GBM;
    const int kz = blockIdx.z;
    const int ty = tid / 16, tx = tid % 16;      // 16x16
    const int tm = ty * 4, tn = tx * 4;

    const float* y0 = g_y2[0];
    const float* y1 = g_y2[1];

    float acc[4][4];
    #pragma unroll
    for (int i = 0; i < 4; i++)
        #pragma unroll
        for (int j = 0; j < 4; j++) acc[i][j] = 0.f;

    const int kbase = kz * KSEG;
    for (int k0 = kbase; k0 < kbase + KSEG; k0 += GBK) {
        #pragma unroll
        for (int i = tid; i < GBM * GBK; i += 256) {
            int m = i / GBK, k = i % GBK;
            size_t off = (size_t)(m0 + m) * T_LEN + k0 + k;
            As[k][m] = y0[off] + y1[off];
        }
        #pragma unroll
        for (int i = tid; i < GBN * GBK; i += 256) {
            int n = i / GBK, k = i % GBK;
            Bs[k][n] = (n0 + n < H_OUT) ? hw[(size_t)(n0 + n) * T_LEN + k0 + k] : 0.f;
        }
        __syncthreads();
        #pragma unroll
        for (int k = 0; k < GBK; k++) {
            float4 a4 = *(const float4*)&As[k][tm];
            float4 b4 = *(const float4*)&Bs[k][tn];
            float av[4] = {a4.x, a4.y, a4.z, a4.w};
            float bv[4] = {b4.x, b4.y, b4.z, b4.w};
            #pragma unroll
            for (int i = 0; i < 4; i++)
                #pragma unroll
                for (int j = 0; j < 4; j++)
                    acc[i][j] = fmaf(av[i], bv[j], acc[i][j]);
        }
        __syncthreads();
    }
    float* outp = g_hp[kz];
    #pragma unroll
    for (int i = 0; i < 4; i++)
        #pragma unroll
        for (int j = 0; j < 4; j++) {
            int m = m0 + tm + i, n = n0 + tn + j;
            if (n < H_OUT) outp[(size_t)m * H_OUT + n] = acc[i][j];
        }
}

__global__ void head_epilogue_kernel(const float* __restrict__ hb,
                                     float* __restrict__ out) {
    int idx = blockIdx.x * blockDim.x + threadIdx.x;
    if (idx >= NB * H_OUT) return;
    int n = idx % H_OUT;
    float v = hb[n];
    #pragma unroll
    for (int kz = 0; kz < KSPLIT; kz++) v += g_hp[kz][idx];
    out[idx] = v;
}

// ---------------------------------------------------------------------------
extern "C" void kernel_launch(void* const* d_in, const int* in_sizes, int n_in,
                              void* d_out, int out_size) {
    const float* x  = (const float*)d_in[0];
    const float* w1 = (const float*)d_in[1];
    const float* b1 = (const float*)d_in[2];
    const float* w2 = (const float*)d_in[3];
    const float* b2 = (const float*)d_in[4];
    const float* hw = (const float*)d_in[5];
    const float* hb = (const float*)d_in[6];
    float* out = (float*)d_out;

    fft_kernel<<<NB, 256>>>(x);
    reduce_amp_kernel<<<NBINS / 256, 256>>>();
    prep_kernel<<<1, NBINS>>>(w1, w2);
    conv_kernel<<<dim3(NCONVBLK, NB, 2), 256>>>(x, b1, b2);
    head_gemm_kernel<<<dim3((H_OUT + GBN - 1) / GBN, NB / GBM, KSPLIT), 256>>>(hw);
    head_epilogue_kernel<<<(NB * H_OUT + 255) / 256, 256>>>(hb, out);
}

// round 11
// speedup vs baseline: 1.7093x; 1.0193x over previous
#include <cuda_runtime.h>
#include <math.h>

#define T_LEN 2048
#define NB    256
#define DMOD  64
#define H_OUT 720
#define NBINS 1024
#define OUTSPAN 928           // outputs per block
#define USPAN  1024           // u slots per block (256 thr x 4)
#define XLEN2  1136           // x staging: USPAN + 2*48 + margin, 4-aligned
#define NCONVBLK 9            // ceil(max padL 8192 / 928)
#define KSPLIT 4
#define KSEG  (T_LEN / KSPLIT)

struct PMeta {
    int S, padL, inner, outer, stepO, stepI, orient;
    unsigned magic;
    float wgt;
};
__device__ PMeta g_pm[2];
__device__ float g_amp[NBINS];
__device__ float g_partial[NBINS * NB];     // [bin][batch] (transposed)
__device__ float g_wp[2][2][DMOD * 9];      // [orient][layer][ch*9+slot]
__device__ float g_y2[2][NB * T_LEN];       // per-period weighted outputs
__device__ float g_hp[KSPLIT][NB * H_OUT];  // head GEMM split-K partials

__device__ __forceinline__ unsigned mdiv(unsigned q, unsigned M) {
    return (unsigned)(((unsigned long long)q * M) >> 32);
}

__device__ __forceinline__ float2 cmul(float2 a, float2 b) {
    return make_float2(a.x * b.x - a.y * b.y, a.x * b.y + a.y * b.x);
}

// ---------------------------------------------------------------------------
// 1) Per-batch 2048-pt FFT, radix-2^2 fused stages (6 syncs), |X[1..1024]|
// ---------------------------------------------------------------------------
__global__ void fft_kernel(const float* __restrict__ x) {
    __shared__ float2 s[T_LEN];
    __shared__ float2 tw[T_LEN / 2];
    int b = blockIdx.x, tid = threadIdx.x;
    const float* xb = x + (size_t)b * T_LEN;
    for (int i = tid; i < T_LEN; i += blockDim.x) {
        int rev = __brev((unsigned)i) >> 21;   // 11-bit reverse
        s[rev] = make_float2(xb[i], 0.f);
    }
    const float base = -6.283185307179586f / (float)T_LEN;
    for (int k = tid; k < T_LEN / 2; k += blockDim.x) {
        float sa, ca;
        __sincosf(base * (float)k, &sa, &ca);
        tw[k] = make_float2(ca, sa);
    }
    __syncthreads();

    // stage m=2 (no twiddle)
    for (int g = tid; g < T_LEN / 2; g += 256) {
        float2 a = s[2 * g], c = s[2 * g + 1];
        s[2 * g]     = make_float2(a.x + c.x, a.y + c.y);
        s[2 * g + 1] = make_float2(a.x - c.x, a.y - c.y);
    }
    __syncthreads();

    // fused stage pairs (m, 2m): m = 4, 16, 64, 256, 1024
    #pragma unroll
    for (int m = 4; m <= 1024; m *= 4) {
        int half = m >> 1;
        int tstep1 = T_LEN / m;          // twiddle stride for stage m
        int tstep2 = T_LEN / (2 * m);    // twiddle stride for stage 2m
        for (int gidx = tid; gidx < T_LEN / 4; gidx += 256) {
            int blk = gidx / half;
            int j   = gidx - blk * half;
            int B   = blk * 2 * m;
            int p0 = B + j, p1 = p0 + half, p2 = p0 + m, p3 = p2 + half;
            float2 wA = tw[j * tstep1];
            float2 wB = tw[j * tstep2];
            float2 u0 = s[p0], u1 = s[p1], u2 = s[p2], u3 = s[p3];
            float2 t1 = cmul(wA, u1);
            float2 a0 = make_float2(u0.x + t1.x, u0.y + t1.y);
            float2 a1 = make_float2(u0.x - t1.x, u0.y - t1.y);
            float2 t3 = cmul(wA, u3);
            float2 a2 = make_float2(u2.x + t3.x, u2.y + t3.y);
            float2 a3 = make_float2(u2.x - t3.x, u2.y - t3.y);
            float2 t2 = cmul(wB, a2);
            float2 t4 = cmul(wB, a3);
            t4 = make_float2(t4.y, -t4.x);       // * (-i)
            s[p0] = make_float2(a0.x + t2.x, a0.y + t2.y);
            s[p2] = make_float2(a0.x - t2.x, a0.y - t2.y);
            s[p1] = make_float2(a1.x + t4.x, a1.y + t4.y);
            s[p3] = make_float2(a1.x - t4.x, a1.y - t4.y);
        }
        __syncthreads();
    }

    for (int k = 1 + tid; k <= NBINS; k += blockDim.x) {
        float2 v = s[k];
        g_partial[(size_t)(k - 1) * NB + b] = sqrtf(v.x * v.x + v.y * v.y);
    }
}

__global__ void reduce_amp_kernel() {
    int k = blockIdx.x * blockDim.x + threadIdx.x;
    if (k >= NBINS) return;
    const float4* p = (const float4*)&g_partial[(size_t)k * NB];
    float acc = 0.f;
    #pragma unroll 8
    for (int i = 0; i < NB / 4; i++) {
        float4 v = p[i];
        acc += v.x + v.y + v.z + v.w;
    }
    g_amp[k] = acc * (1.f / (float)NB);
}

// ---------------------------------------------------------------------------
// 2) prep: weight permutations (both orientations) + top-2 + per-period meta
// ---------------------------------------------------------------------------
__global__ void prep_kernel(const float* __restrict__ w1,
                            const float* __restrict__ w2) {
    __shared__ float sv[NBINS];
    __shared__ int   si[NBINS];
    __shared__ float b_v; __shared__ int b_i;
    int tid = threadIdx.x;   // 1024

    for (int idx = tid; idx < 2 * 2 * DMOD * 9; idx += 1024) {
        int orient = idx / (2 * DMOD * 9);
        int rem    = idx - orient * 2 * DMOD * 9;
        int layer  = rem / (DMOD * 9);
        int i      = rem - layer * DMOD * 9;
        int ch = i / 9, s = i - ch * 9;
        int g = s / 3, di = s % 3 - 1;
        int do_ = (g == 0) ? 0 : (g == 1 ? 1 : -1);
        int src = orient ? (ch * 9 + (do_ + 1) * 3 + (di + 1))
                         : (ch * 9 + (di + 1) * 3 + (do_ + 1));
        g_wp[orient][layer][i] = layer ? w2[src] : w1[src];
    }

    sv[tid] = g_amp[tid]; si[tid] = tid;
    __syncthreads();
    for (int s = NBINS / 2; s > 0; s >>= 1) {
        if (tid < s) {
            float v2 = sv[tid + s]; int i2 = si[tid + s];
            if (v2 > sv[tid] || (v2 == sv[tid] && i2 < si[tid])) { sv[tid] = v2; si[tid] = i2; }
        }
        __syncthreads();
    }
    if (tid == 0) { b_v = sv[0]; b_i = si[0]; }
    __syncthreads();
    float v1 = b_v; int i1 = b_i;
    __syncthreads();

    sv[tid] = (tid == i1) ? -1e30f : g_amp[tid]; si[tid] = tid;
    __syncthreads();
    for (int s = NBINS / 2; s > 0; s >>= 1) {
        if (tid < s) {
            float v2 = sv[tid + s]; int i2 = si[tid + s];
            if (v2 > sv[tid] || (v2 == sv[tid] && i2 < si[tid])) { sv[tid] = v2; si[tid] = i2; }
        }
        __syncthreads();
    }
    if (tid == 0) {
        float v2 = sv[0]; int i2 = si[0];
        float e2 = __expf(v2 - v1);
        float inv = 1.f / (1.f + e2);
        float wgts[2] = { inv, e2 * inv };
        int   idxs[2] = { i1, i2 };
        for (int t = 0; t < 2; t++) {
            int f = idxs[t] + 1;
            int P = (int)llrint((double)T_LEN / (double)f); if (P < 1) P = 1;
            int cols = (T_LEN + P - 1) / P;
            int orient = (P <= cols) ? 0 : 1;
            int inner = orient ? cols : P;
            int outer = orient ? P : cols;
            int S = (inner + 2 + 3) & ~3;
            PMeta pm;
            pm.S = S; pm.padL = outer * S;
            pm.inner = inner; pm.outer = outer;
            pm.stepO = orient ? 1 : P;
            pm.stepI = orient ? P : 1;
            pm.orient = orient;
            pm.magic = 0xFFFFFFFFu / (unsigned)S + 1u;
            pm.wgt = wgts[t];
            g_pm[t] = pm;
        }
    }
}

__device__ __forceinline__ float gelu_fast(float v) {
    float v2 = v * v;
    float u  = v * fmaf(0.035677408136f, v2, 0.7978845608f);
    float t;
    asm("tanh.approx.f32 %0, %1;" : "=f"(t) : "f"(u));
    return v * fmaf(0.5f, t, 0.5f);
}

// ---------------------------------------------------------------------------
// 3) Register-resident fused conv1 -> GELU -> conv2 (3 CTAs/SM)
// ---------------------------------------------------------------------------
__global__ __launch_bounds__(256, 3) void conv_kernel(
        const float* __restrict__ x,
        const float* __restrict__ b1,
        const float* __restrict__ b2) {
    const int period = blockIdx.z;
    const PMeta pm = g_pm[period];
    const int S = pm.S, inner = pm.inner, padL = pm.padL;
    const int stepO = pm.stepO, stepI = pm.stepI;
    const unsigned M = pm.magic;

    if (blockIdx.x * OUTSPAN >= padL) return;
    const int qb  = blockIdx.x * OUTSPAN - 48;   // u-span start (4-aligned)
    const int b   = blockIdx.y;
    const int tid = threadIdx.x;

    __shared__ float xs[XLEN2];
    __shared__ float sUm[USPAN];
    __shared__ float sUp[USPAN];
    __shared__ __align__(16) float w1p[DMOD][12];
    __shared__ __align__(16) float w2p[DMOD][12];
    __shared__ float b1s[DMOD];
    __shared__ float b2s_s;

    const float* w1g = g_wp[pm.orient][0];
    const float* w2g = g_wp[pm.orient][1];
    for (int i = tid; i < DMOD * 9; i += 256) {
        int ch = i / 9, j = i - ch * 9;
        w1p[ch][j] = w1g[i];
        w2p[ch][j] = w2g[i];
    }
    if (tid < DMOD) b1s[tid] = b1[tid];
    if (tid == 0)   b2s_s = b2[0];

    // stage x over padded q in [qb - 52, qb - 52 + XLEN2)
    const float* xb = x + (size_t)b * T_LEN;
    for (int i = tid; i < XLEN2; i += 256) {
        int q = qb - 52 + i;
        float v = 0.f;
        if (q >= 0 && q < padL) {
            unsigned o = mdiv((unsigned)q, M);
            int i_ = q - (int)o * S - 1;
            if (i_ >= 0 && i_ < inner) {
                int n = (int)o * stepO + i_ * stepI;
                if (n < T_LEN) v = xb[n];
            }
        }
        xs[i] = v;
    }
    __syncthreads();

    // x taps into registers: rows do=-1,0,+1; inner offsets ju-2 .. ju+5
    float r0[8], r1[8], r2[8];
    {
        const float* xr = xs + tid * 4 + 50;     // index of (ju-2), 2-aligned
        #pragma unroll
        for (int k = 0; k < 4; k++) {
            float2 v;
            v = *(const float2*)(xr + 2 * k);       r1[2*k] = v.x; r1[2*k+1] = v.y;
            v = *(const float2*)(xr + S + 2 * k);   r2[2*k] = v.x; r2[2*k+1] = v.y;
            v = *(const float2*)(xr - S + 2 * k);   r0[2*k] = v.x; r0[2*k+1] = v.y;
        }
    }

    // h-position masks (6) and output metadata (4)
    float m[6];
    #pragma unroll
    for (int t = 0; t < 6; t++) {
        int q = qb + tid * 4 - 1 + t;
        bool v = false;
        if (q >= 0 && q < padL) {
            unsigned o = mdiv((unsigned)q, M);
            int i_ = q - (int)o * S - 1;
            v = (i_ >= 0 && i_ < inner);
        }
        m[t] = v ? 1.f : 0.f;
    }
    int on[4]; bool ov[4]; bool anyv = false;
    #pragma unroll
    for (int r = 0; r < 4; r++) {
        int lj = tid * 4 + r;
        int q  = qb + lj;
        ov[r] = false; on[r] = 0;
        if (lj >= 48 && lj < 48 + OUTSPAN && q < padL) {
            unsigned o = mdiv((unsigned)q, M);
            int i_ = q - (int)o * S - 1;
            if (i_ >= 0 && i_ < inner) {
                int n = (int)o * stepO + i_ * stepI;
                if (n < T_LEN) { ov[r] = true; on[r] = n; anyv = true; }
            }
        }
    }

    float U0[4] = {0.f, 0.f, 0.f, 0.f};
    float Up[4] = {0.f, 0.f, 0.f, 0.f};
    float Um[4] = {0.f, 0.f, 0.f, 0.f};

    #pragma unroll 2
    for (int ch = 0; ch < DMOD; ch++) {
        const float4* w1r = (const float4*)w1p[ch];
        float4 wa = w1r[0], wb = w1r[1], wc = w1r[2];
        float bias = b1s[ch];
        float h[6];
        #pragma unroll
        for (int t = 0; t < 6; t++) {
            float a = bias;
            a = fmaf(wa.x, r1[t],     a);
            a = fmaf(wa.y, r1[t + 1], a);
            a = fmaf(wa.z, r1[t + 2], a);
            a = fmaf(wa.w, r2[t],     a);
            a = fmaf(wb.x, r2[t + 1], a);
            a = fmaf(wb.y, r2[t + 2], a);
            a = fmaf(wb.z, r0[t],     a);
            a = fmaf(wb.w, r0[t + 1], a);
            a = fmaf(wc.x, r0[t + 2], a);
            h[t] = gelu_fast(a) * m[t];
        }
        const float4* w2r = (const float4*)w2p[ch];
        float4 va = w2r[0], vb = w2r[1], vc = w2r[2];
        #pragma unroll
        for (int r = 0; r < 4; r++) {
            U0[r] = fmaf(va.x, h[r],     U0[r]);
            U0[r] = fmaf(va.y, h[r + 1], U0[r]);
            U0[r] = fmaf(va.z, h[r + 2], U0[r]);
            Up[r] = fmaf(va.w, h[r],     Up[r]);
            Up[r] = fmaf(vb.x, h[r + 1], Up[r]);
            Up[r] = fmaf(vb.y, h[r + 2], Up[r]);
            Um[r] = fmaf(vb.z, h[r],     Um[r]);
            Um[r] = fmaf(vb.w, h[r + 1], Um[r]);
            Um[r] = fmaf(vc.x, h[r + 2], Um[r]);
        }
    }

    // one-time cross-row exchange
    *(float4*)(sUm + tid * 4) = make_float4(Um[0], Um[1], Um[2], Um[3]);
    *(float4*)(sUp + tid * 4) = make_float4(Up[0], Up[1], Up[2], Up[3]);
    __syncthreads();

    if (anyv) {
        float* yout = g_y2[period] + (size_t)b * T_LEN;
        #pragma unroll
        for (int r = 0; r < 4; r++) {
            if (ov[r]) {
                int lj = tid * 4 + r;
                float val = b2s_s + U0[r] + sUm[lj - S] + sUp[lj + S];
                yout[on[r]] = pm.wgt * val;
            }
        }
    }
}

// ---------------------------------------------------------------------------
// 4) Head GEMM, split-K
// ---------------------------------------------------------------------------
#define GBM 64
#define GBN 64
#define GBK 32
__global__ __launch_bounds__(256) void head_gemm_kernel(
        const float* __restrict__ hw) {
    __shared__ __align__(16) float As[GBK][GBM];
    __shared__ __align__(16) float Bs[GBK][GBN];
    const int tid = threadIdx.x;
    const int n0 = blockIdx.x * GBN, m0 = blockIdx.y * GBM;
    const int kz = blockIdx.z;
    const int ty = tid / 16, tx = tid % 16;      // 16x16
    const int tm = ty * 4, tn = tx * 4;

    const float* y0 = g_y2[0];
    const float* y1 = g_y2[1];

    float acc[4][4];
    #pragma unroll
    for (int i = 0; i < 4; i++)
        #pragma unroll
        for (int j = 0; j < 4; j++) acc[i][j] = 0.f;

    const int kbase = kz * KSEG;
    for (int k0 = kbase; k0 < kbase + KSEG; k0 += GBK) {
        #pragma unroll
        for (int i = tid; i < GBM * GBK; i += 256) {
            int m = i / GBK, k = i % GBK;
            size_t off = (size_t)(m0 + m) * T_LEN + k0 + k;
            As[k][m] = y0[off] + y1[off];
        }
        #pragma unroll
        for (int i = tid; i < GBN * GBK; i += 256) {
            int n = i / GBK, k = i % GBK;
            Bs[k][n] = (n0 + n < H_OUT) ? hw[(size_t)(n0 + n) * T_LEN + k0 + k] : 0.f;
        }
        __syncthreads();
        #pragma unroll
        for (int k = 0; k < GBK; k++) {
            float4 a4 = *(const float4*)&As[k][tm];
            float4 b4 = *(const float4*)&Bs[k][tn];
            float av[4] = {a4.x, a4.y, a4.z, a4.w};
            float bv[4] = {b4.x, b4.y, b4.z, b4.w};
            #pragma unroll
            for (int i = 0; i < 4; i++)
                #pragma unroll
                for (int j = 0; j < 4; j++)
                    acc[i][j] = fmaf(av[i], bv[j], acc[i][j]);
        }
        __syncthreads();
    }
    float* outp = g_hp[kz];
    #pragma unroll
    for (int i = 0; i < 4; i++)
        #pragma unroll
        for (int j = 0; j < 4; j++) {
            int m = m0 + tm + i, n = n0 + tn + j;
            if (n < H_OUT) outp[(size_t)m * H_OUT + n] = acc[i][j];
        }
}

__global__ void head_epilogue_kernel(const float* __restrict__ hb,
                                     float* __restrict__ out) {
    int idx = blockIdx.x * blockDim.x + threadIdx.x;
    if (idx >= NB * H_OUT) return;
    int n = idx % H_OUT;
    float v = hb[n];
    #pragma unroll
    for (int kz = 0; kz < KSPLIT; kz++) v += g_hp[kz][idx];
    out[idx] = v;
}

// ---------------------------------------------------------------------------
extern "C" void kernel_launch(void* const* d_in, const int* in_sizes, int n_in,
                              void* d_out, int out_size) {
    const float* x  = (const float*)d_in[0];
    const float* w1 = (const float*)d_in[1];
    const float* b1 = (const float*)d_in[2];
    const float* w2 = (const float*)d_in[3];
    const float* b2 = (const float*)d_in[4];
    const float* hw = (const float*)d_in[5];
    const float* hb = (const float*)d_in[6];
    float* out = (float*)d_out;

    fft_kernel<<<NB, 256>>>(x);
    reduce_amp_kernel<<<NBINS / 256, 256>>>();
    prep_kernel<<<1, NBINS>>>(w1, w2);
    conv_kernel<<<dim3(NCONVBLK, NB, 2), 256>>>(x, b1, b2);
    head_gemm_kernel<<<dim3((H_OUT + GBN - 1) / GBN, NB / GBM, KSPLIT), 256>>>(hw);
    head_epilogue_kernel<<<(NB * H_OUT + 255) / 256, 256>>>(hb, out);
}

// round 12
// speedup vs baseline: 1.7669x; 1.0337x over previous
#include <cuda_runtime.h>
#include <math.h>

#define T_LEN 2048
#define NB    256
#define DMOD  64
#define H_OUT 720
#define NBINS 1024
#define OUTSPAN 928           // outputs per block
#define USPAN  1024           // u slots per block (256 thr x 4)
#define XLEN2  1136           // x staging
#define NCONVBLK 9            // ceil(max padL 8192 / 928)
#define KSPLIT 4
#define KSEG  (T_LEN / KSPLIT)

typedef unsigned long long ull;

struct PMeta {
    int S, padL, inner, outer, stepO, stepI, orient;
    unsigned magic;
    float wgt;
};
__device__ PMeta g_pm[2];
__device__ float g_amp[NBINS];
__device__ float g_partial[NBINS * NB];      // [bin][batch]
__device__ float2 g_wq[2][2][(DMOD/2) * 9];  // [orient][layer][pair*9+slot] = (w[2p][s], w[2p+1][s])
__device__ float2 g_b1q[DMOD / 2];
__device__ float g_y2[2][NB * T_LEN];
__device__ float g_hp[KSPLIT][NB * H_OUT];

__device__ __forceinline__ unsigned mdiv(unsigned q, unsigned M) {
    return (unsigned)(((unsigned long long)q * M) >> 32);
}
__device__ __forceinline__ float2 cmul(float2 a, float2 b) {
    return make_float2(a.x * b.x - a.y * b.y, a.x * b.y + a.y * b.x);
}

// ---- f32x2 packed helpers (Blackwell) ----
__device__ __forceinline__ ull pack2(float lo, float hi) {
    ull r; asm("mov.b64 %0, {%1, %2};" : "=l"(r) : "f"(lo), "f"(hi)); return r;
}
__device__ __forceinline__ ull bcast2(float v) { return pack2(v, v); }
__device__ __forceinline__ void unpack2(ull v, float& lo, float& hi) {
    asm("mov.b64 {%0, %1}, %2;" : "=f"(lo), "=f"(hi) : "l"(v));
}
__device__ __forceinline__ ull fma2(ull a, ull b, ull c) {
    ull d; asm("fma.rn.f32x2 %0, %1, %2, %3;" : "=l"(d) : "l"(a), "l"(b), "l"(c)); return d;
}
__device__ __forceinline__ ull mul2(ull a, ull b) {
    ull d; asm("mul.rn.f32x2 %0, %1, %2;" : "=l"(d) : "l"(a), "l"(b)); return d;
}

// ---------------------------------------------------------------------------
// 1) Per-batch 2048-pt FFT, radix-2^2 fused stages
// ---------------------------------------------------------------------------
__global__ void fft_kernel(const float* __restrict__ x) {
    __shared__ float2 s[T_LEN];
    __shared__ float2 tw[T_LEN / 2];
    int b = blockIdx.x, tid = threadIdx.x;
    const float* xb = x + (size_t)b * T_LEN;
    for (int i = tid; i < T_LEN; i += blockDim.x) {
        int rev = __brev((unsigned)i) >> 21;
        s[rev] = make_float2(xb[i], 0.f);
    }
    const float base = -6.283185307179586f / (float)T_LEN;
    for (int k = tid; k < T_LEN / 2; k += blockDim.x) {
        float sa, ca;
        __sincosf(base * (float)k, &sa, &ca);
        tw[k] = make_float2(ca, sa);
    }
    __syncthreads();

    for (int g = tid; g < T_LEN / 2; g += 256) {
        float2 a = s[2 * g], c = s[2 * g + 1];
        s[2 * g]     = make_float2(a.x + c.x, a.y + c.y);
        s[2 * g + 1] = make_float2(a.x - c.x, a.y - c.y);
    }
    __syncthreads();

    #pragma unroll
    for (int m = 4; m <= 1024; m *= 4) {
        int half = m >> 1;
        int tstep1 = T_LEN / m;
        int tstep2 = T_LEN / (2 * m);
        for (int gidx = tid; gidx < T_LEN / 4; gidx += 256) {
            int blk = gidx / half;
            int j   = gidx - blk * half;
            int B   = blk * 2 * m;
            int p0 = B + j, p1 = p0 + half, p2 = p0 + m, p3 = p2 + half;
            float2 wA = tw[j * tstep1];
            float2 wB = tw[j * tstep2];
            float2 u0 = s[p0], u1 = s[p1], u2 = s[p2], u3 = s[p3];
            float2 t1 = cmul(wA, u1);
            float2 a0 = make_float2(u0.x + t1.x, u0.y + t1.y);
            float2 a1 = make_float2(u0.x - t1.x, u0.y - t1.y);
            float2 t3 = cmul(wA, u3);
            float2 a2 = make_float2(u2.x + t3.x, u2.y + t3.y);
            float2 a3 = make_float2(u2.x - t3.x, u2.y - t3.y);
            float2 t2 = cmul(wB, a2);
            float2 t4 = cmul(wB, a3);
            t4 = make_float2(t4.y, -t4.x);
            s[p0] = make_float2(a0.x + t2.x, a0.y + t2.y);
            s[p2] = make_float2(a0.x - t2.x, a0.y - t2.y);
            s[p1] = make_float2(a1.x + t4.x, a1.y + t4.y);
            s[p3] = make_float2(a1.x - t4.x, a1.y - t4.y);
        }
        __syncthreads();
    }

    for (int k = 1 + tid; k <= NBINS; k += blockDim.x) {
        float2 v = s[k];
        g_partial[(size_t)(k - 1) * NB + b] = sqrtf(v.x * v.x + v.y * v.y);
    }
}

__global__ void reduce_amp_kernel() {
    int k = blockIdx.x * blockDim.x + threadIdx.x;
    if (k >= NBINS) return;
    const float4* p = (const float4*)&g_partial[(size_t)k * NB];
    float acc = 0.f;
    #pragma unroll 8
    for (int i = 0; i < NB / 4; i++) {
        float4 v = p[i];
        acc += v.x + v.y + v.z + v.w;
    }
    g_amp[k] = acc * (1.f / (float)NB);
}

// ---------------------------------------------------------------------------
// 2) prep: channel-paired weight packs (both orientations) + top-2 + meta
//    Slot order: groups [do=0][do=+1][do=-1], within each di=-1,0,+1
// ---------------------------------------------------------------------------
__global__ void prep_kernel(const float* __restrict__ w1,
                            const float* __restrict__ w2,
                            const float* __restrict__ b1) {
    __shared__ float sv[NBINS];
    __shared__ int   si[NBINS];
    __shared__ float b_v; __shared__ int b_i;
    int tid = threadIdx.x;   // 1024

    const int NP = DMOD / 2;
    for (int idx = tid; idx < 2 * 2 * NP * 9; idx += 1024) {
        int orient = idx / (2 * NP * 9);
        int rem    = idx - orient * 2 * NP * 9;
        int layer  = rem / (NP * 9);
        int i      = rem - layer * NP * 9;
        int p = i / 9, s = i - p * 9;
        int g = s / 3, di = s % 3 - 1;
        int do_ = (g == 0) ? 0 : (g == 1 ? 1 : -1);
        int off = orient ? ((do_ + 1) * 3 + (di + 1)) : ((di + 1) * 3 + (do_ + 1));
        const float* w = layer ? w2 : w1;
        g_wq[orient][layer][i] = make_float2(w[(2 * p) * 9 + off], w[(2 * p + 1) * 9 + off]);
    }
    if (tid < NP) g_b1q[tid] = make_float2(b1[2 * tid], b1[2 * tid + 1]);

    sv[tid] = g_amp[tid]; si[tid] = tid;
    __syncthreads();
    for (int s = NBINS / 2; s > 0; s >>= 1) {
        if (tid < s) {
            float v2 = sv[tid + s]; int i2 = si[tid + s];
            if (v2 > sv[tid] || (v2 == sv[tid] && i2 < si[tid])) { sv[tid] = v2; si[tid] = i2; }
        }
        __syncthreads();
    }
    if (tid == 0) { b_v = sv[0]; b_i = si[0]; }
    __syncthreads();
    float v1 = b_v; int i1 = b_i;
    __syncthreads();

    sv[tid] = (tid == i1) ? -1e30f : g_amp[tid]; si[tid] = tid;
    __syncthreads();
    for (int s = NBINS / 2; s > 0; s >>= 1) {
        if (tid < s) {
            float v2 = sv[tid + s]; int i2 = si[tid + s];
            if (v2 > sv[tid] || (v2 == sv[tid] && i2 < si[tid])) { sv[tid] = v2; si[tid] = i2; }
        }
        __syncthreads();
    }
    if (tid == 0) {
        float v2 = sv[0]; int i2 = si[0];
        float e2 = __expf(v2 - v1);
        float inv = 1.f / (1.f + e2);
        float wgts[2] = { inv, e2 * inv };
        int   idxs[2] = { i1, i2 };
        for (int t = 0; t < 2; t++) {
            int f = idxs[t] + 1;
            int P = (int)llrint((double)T_LEN / (double)f); if (P < 1) P = 1;
            int cols = (T_LEN + P - 1) / P;
            int orient = (P <= cols) ? 0 : 1;
            int inner = orient ? cols : P;
            int outer = orient ? P : cols;
            int S = (inner + 2 + 3) & ~3;
            PMeta pm;
            pm.S = S; pm.padL = outer * S;
            pm.inner = inner; pm.outer = outer;
            pm.stepO = orient ? 1 : P;
            pm.stepI = orient ? P : 1;
            pm.orient = orient;
            pm.magic = 0xFFFFFFFFu / (unsigned)S + 1u;
            pm.wgt = wgts[t];
            g_pm[t] = pm;
        }
    }
}

// packed GELU (tanh scalar per lane)
__device__ __forceinline__ ull gelu2(ull vq, ull C0, ull C1, ull HALF) {
    ull v2q = mul2(vq, vq);
    ull uq  = mul2(vq, fma2(C1, v2q, C0));
    float ul, uh;
    unpack2(uq, ul, uh);
    float tl, th;
    asm("tanh.approx.f32 %0, %1;" : "=f"(tl) : "f"(ul));
    asm("tanh.approx.f32 %0, %1;" : "=f"(th) : "f"(uh));
    ull tq = pack2(tl, th);
    return mul2(vq, fma2(HALF, tq, HALF));
}

// ---------------------------------------------------------------------------
// 3) f32x2 channel-paired register-resident fused conv
// ---------------------------------------------------------------------------
__global__ __launch_bounds__(256, 2) void conv_kernel(
        const float* __restrict__ x,
        const float* __restrict__ b2) {
    const int period = blockIdx.z;
    const PMeta pm = g_pm[period];
    const int S = pm.S, inner = pm.inner, padL = pm.padL;
    const int stepO = pm.stepO, stepI = pm.stepI;
    const unsigned M = pm.magic;

    if (blockIdx.x * OUTSPAN >= padL) return;
    const int qb  = blockIdx.x * OUTSPAN - 48;
    const int b   = blockIdx.y;
    const int tid = threadIdx.x;

    __shared__ float xs[XLEN2];
    __shared__ float sUm[USPAN];
    __shared__ float sUp[USPAN];
    __shared__ __align__(16) ull w1s[(DMOD/2) * 9];
    __shared__ __align__(16) ull w2s[(DMOD/2) * 9];
    __shared__ ull b1s[DMOD / 2];
    __shared__ float b2s_s;

    {
        const ull* gw1 = (const ull*)g_wq[pm.orient][0];
        const ull* gw2 = (const ull*)g_wq[pm.orient][1];
        for (int i = tid; i < (DMOD/2) * 9; i += 256) {
            w1s[i] = gw1[i];
            w2s[i] = gw2[i];
        }
        if (tid < DMOD / 2) b1s[tid] = ((const ull*)g_b1q)[tid];
        if (tid == 0) b2s_s = b2[0];
    }

    // stage x
    const float* xb = x + (size_t)b * T_LEN;
    for (int i = tid; i < XLEN2; i += 256) {
        int q = qb - 52 + i;
        float v = 0.f;
        if (q >= 0 && q < padL) {
            unsigned o = mdiv((unsigned)q, M);
            int i_ = q - (int)o * S - 1;
            if (i_ >= 0 && i_ < inner) {
                int n = (int)o * stepO + i_ * stepI;
                if (n < T_LEN) v = xb[n];
            }
        }
        xs[i] = v;
    }
    __syncthreads();

    // broadcast-packed taps: rows do=-1,0,+1, inner offsets ju-2..ju+5
    ull T0[8], T1[8], T2[8];
    {
        const float* xr = xs + tid * 4 + 50;
        #pragma unroll
        for (int k = 0; k < 8; k++) {
            T1[k] = bcast2(xr[k]);
            T2[k] = bcast2(xr[S + k]);
            T0[k] = bcast2(xr[-S + k]);
        }
    }

    // masks and output metadata
    ull Mq[6];
    #pragma unroll
    for (int t = 0; t < 6; t++) {
        int q = qb + tid * 4 - 1 + t;
        bool v = false;
        if (q >= 0 && q < padL) {
            unsigned o = mdiv((unsigned)q, M);
            int i_ = q - (int)o * S - 1;
            v = (i_ >= 0 && i_ < inner);
        }
        Mq[t] = bcast2(v ? 1.f : 0.f);
    }
    int on[4]; bool ov[4]; bool anyv = false;
    #pragma unroll
    for (int r = 0; r < 4; r++) {
        int lj = tid * 4 + r;
        int q  = qb + lj;
        ov[r] = false; on[r] = 0;
        if (lj >= 48 && lj < 48 + OUTSPAN && q < padL) {
            unsigned o = mdiv((unsigned)q, M);
            int i_ = q - (int)o * S - 1;
            if (i_ >= 0 && i_ < inner) {
                int n = (int)o * stepO + i_ * stepI;
                if (n < T_LEN) { ov[r] = true; on[r] = n; anyv = true; }
            }
        }
    }

    const ull C0   = bcast2(0.7978845608f);
    const ull C1   = bcast2(0.035677408136f);
    const ull HALF = bcast2(0.5f);

    ull U0q[4], Upq[4], Umq[4];
    #pragma unroll
    for (int r = 0; r < 4; r++) { U0q[r] = 0ull; Upq[r] = 0ull; Umq[r] = 0ull; }

    for (int pch = 0; pch < DMOD / 2; pch++) {
        const ull* w1r = &w1s[pch * 9];
        const ull* w2r = &w2s[pch * 9];
        ull bq = b1s[pch];
        ull hq[6];
        #pragma unroll
        for (int t = 0; t < 6; t++) {
            ull a = bq;
            a = fma2(w1r[0], T1[t],     a);
            a = fma2(w1r[1], T1[t + 1], a);
            a = fma2(w1r[2], T1[t + 2], a);
            a = fma2(w1r[3], T2[t],     a);
            a = fma2(w1r[4], T2[t + 1], a);
            a = fma2(w1r[5], T2[t + 2], a);
            a = fma2(w1r[6], T0[t],     a);
            a = fma2(w1r[7], T0[t + 1], a);
            a = fma2(w1r[8], T0[t + 2], a);
            hq[t] = mul2(gelu2(a, C0, C1, HALF), Mq[t]);
        }
        #pragma unroll
        for (int r = 0; r < 4; r++) {
            U0q[r] = fma2(w2r[0], hq[r],     U0q[r]);
            U0q[r] = fma2(w2r[1], hq[r + 1], U0q[r]);
            U0q[r] = fma2(w2r[2], hq[r + 2], U0q[r]);
            Upq[r] = fma2(w2r[3], hq[r],     Upq[r]);
            Upq[r] = fma2(w2r[4], hq[r + 1], Upq[r]);
            Upq[r] = fma2(w2r[5], hq[r + 2], Upq[r]);
            Umq[r] = fma2(w2r[6], hq[r],     Umq[r]);
            Umq[r] = fma2(w2r[7], hq[r + 1], Umq[r]);
            Umq[r] = fma2(w2r[8], hq[r + 2], Umq[r]);
        }
    }

    // lane-sum and one-time cross-row exchange
    float U0[4], Um[4], Up[4];
    #pragma unroll
    for (int r = 0; r < 4; r++) {
        float lo, hi;
        unpack2(U0q[r], lo, hi); U0[r] = lo + hi;
        unpack2(Upq[r], lo, hi); Up[r] = lo + hi;
        unpack2(Umq[r], lo, hi); Um[r] = lo + hi;
    }
    *(float4*)(sUm + tid * 4) = make_float4(Um[0], Um[1], Um[2], Um[3]);
    *(float4*)(sUp + tid * 4) = make_float4(Up[0], Up[1], Up[2], Up[3]);
    __syncthreads();

    if (anyv) {
        float* yout = g_y2[period] + (size_t)b * T_LEN;
        #pragma unroll
        for (int r = 0; r < 4; r++) {
            if (ov[r]) {
                int lj = tid * 4 + r;
                float val = b2s_s + U0[r] + sUm[lj - S] + sUp[lj + S];
                yout[on[r]] = pm.wgt * val;
            }
        }
    }
}

// ---------------------------------------------------------------------------
// 4) Head GEMM, split-K
// ---------------------------------------------------------------------------
#define GBM 64
#define GBN 64
#define GBK 32
__global__ __launch_bounds__(256) void head_gemm_kernel(
        const float* __restrict__ hw) {
    __shared__ __align__(16) float As[GBK][GBM];
    __shared__ __align__(16) float Bs[GBK][GBN];
    const int tid = threadIdx.x;
    const int n0 = blockIdx.x * GBN, m0 = blockIdx.y * GBM;
    const int kz = blockIdx.z;
    const int ty = tid / 16, tx = tid % 16;
    const int tm = ty * 4, tn = tx * 4;

    const float* y0 = g_y2[0];
    const float* y1 = g_y2[1];

    float acc[4][4];
    #pragma unroll
    for (int i = 0; i < 4; i++)
        #pragma unroll
        for (int j = 0; j < 4; j++) acc[i][j] = 0.f;

    const int kbase = kz * KSEG;
    for (int k0 = kbase; k0 < kbase + KSEG; k0 += GBK) {
        #pragma unroll
        for (int i = tid; i < GBM * GBK; i += 256) {
            int m = i / GBK, k = i % GBK;
            size_t off = (size_t)(m0 + m) * T_LEN + k0 + k;
            As[k][m] = y0[off] + y1[off];
        }
        #pragma unroll
        for (int i = tid; i < GBN * GBK; i += 256) {
            int n = i / GBK, k = i % GBK;
            Bs[k][n] = (n0 + n < H_OUT) ? hw[(size_t)(n0 + n) * T_LEN + k0 + k] : 0.f;
        }
        __syncthreads();
        #pragma unroll
        for (int k = 0; k < GBK; k++) {
            float4 a4 = *(const float4*)&As[k][tm];
            float4 b4 = *(const float4*)&Bs[k][tn];
            float av[4] = {a4.x, a4.y, a4.z, a4.w};
            float bv[4] = {b4.x, b4.y, b4.z, b4.w};
            #pragma unroll
            for (int i = 0; i < 4; i++)
                #pragma unroll
                for (int j = 0; j < 4; j++)
                    acc[i][j] = fmaf(av[i], bv[j], acc[i][j]);
        }
        __syncthreads();
    }
    float* outp = g_hp[kz];
    #pragma unroll
    for (int i = 0; i < 4; i++)
        #pragma unroll
        for (int j = 0; j < 4; j++) {
            int m = m0 + tm + i, n = n0 + tn + j;
            if (n < H_OUT) outp[(size_t)m * H_OUT + n] = acc[i][j];
        }
}

__global__ void head_epilogue_kernel(const float* __restrict__ hb,
                                     float* __restrict__ out) {
    int idx = blockIdx.x * blockDim.x + threadIdx.x;
    if (idx >= NB * H_OUT) return;
    int n = idx % H_OUT;
    float v = hb[n];
    #pragma unroll
    for (int kz = 0; kz < KSPLIT; kz++) v += g_hp[kz][idx];
    out[idx] = v;
}

// ---------------------------------------------------------------------------
extern "C" void kernel_launch(void* const* d_in, const int* in_sizes, int n_in,
                              void* d_out, int out_size) {
    const float* x  = (const float*)d_in[0];
    const float* w1 = (const float*)d_in[1];
    const float* b1 = (const float*)d_in[2];
    const float* w2 = (const float*)d_in[3];
    const float* b2 = (const float*)d_in[4];
    const float* hw = (const float*)d_in[5];
    const float* hb = (const float*)d_in[6];
    float* out = (float*)d_out;

    fft_kernel<<<NB, 256>>>(x);
    reduce_amp_kernel<<<NBINS / 256, 256>>>();
    prep_kernel<<<1, NBINS>>>(w1, w2, b1);
    conv_kernel<<<dim3(NCONVBLK, NB, 2), 256>>>(x, b2);
    head_gemm_kernel<<<dim3((H_OUT + GBN - 1) / GBN, NB / GBM, KSPLIT), 256>>>(hw);
    head_epilogue_kernel<<<(NB * H_OUT + 255) / 256, 256>>>(hb, out);
}

// round 13
// speedup vs baseline: 1.9437x; 1.1000x over previous
#include <cuda_runtime.h>
#include <math.h>

#define T_LEN 2048
#define NB    256
#define DMOD  64
#define H_OUT 720
#define NBINS 1024
#define OUTSPAN 928
#define USPAN  1024
#define XLEN2  1136
#define NCONVBLK 9
#define KSPLIT 8
#define KSEG  (T_LEN / KSPLIT)

typedef unsigned long long ull;

struct PMeta {
    int S, padL, inner, outer, stepO, stepI, orient;
    unsigned magic;
    float wgt;
};
__device__ PMeta g_pm[2];
__device__ float g_amp[NBINS];
__device__ float g_partial[NBINS * NB];
__device__ float2 g_wq[2][2][(DMOD/2) * 9];
__device__ float2 g_b1q[DMOD / 2];
__device__ float g_y2[2][NB * T_LEN];
__device__ float g_hp[KSPLIT][NB * H_OUT];

__device__ __forceinline__ unsigned mdiv(unsigned q, unsigned M) {
    return (unsigned)(((unsigned long long)q * M) >> 32);
}
__device__ __forceinline__ float2 cmul(float2 a, float2 b) {
    return make_float2(a.x * b.x - a.y * b.y, a.x * b.y + a.y * b.x);
}

// ---- f32x2 packed helpers ----
__device__ __forceinline__ ull pack2(float lo, float hi) {
    ull r; asm("mov.b64 %0, {%1, %2};" : "=l"(r) : "f"(lo), "f"(hi)); return r;
}
__device__ __forceinline__ ull bcast2(float v) { return pack2(v, v); }
__device__ __forceinline__ void unpack2(ull v, float& lo, float& hi) {
    asm("mov.b64 {%0, %1}, %2;" : "=f"(lo), "=f"(hi) : "l"(v));
}
__device__ __forceinline__ ull fma2(ull a, ull b, ull c) {
    ull d; asm("fma.rn.f32x2 %0, %1, %2, %3;" : "=l"(d) : "l"(a), "l"(b), "l"(c)); return d;
}
__device__ __forceinline__ ull mul2(ull a, ull b) {
    ull d; asm("mul.rn.f32x2 %0, %1, %2;" : "=l"(d) : "l"(a), "l"(b)); return d;
}

// ---------------------------------------------------------------------------
// 1) Per-batch 2048-pt FFT, radix-2^2 fused, 512 threads (1 bfly/thread)
// ---------------------------------------------------------------------------
__global__ __launch_bounds__(512) void fft_kernel(const float* __restrict__ x) {
    __shared__ float2 s[T_LEN];
    __shared__ float2 tw[T_LEN / 2];
    int b = blockIdx.x, tid = threadIdx.x;
    const float* xb = x + (size_t)b * T_LEN;
    for (int i = tid; i < T_LEN; i += 512) {
        int rev = __brev((unsigned)i) >> 21;
        s[rev] = make_float2(xb[i], 0.f);
    }
    const float base = -6.283185307179586f / (float)T_LEN;
    for (int k = tid; k < T_LEN / 2; k += 512) {
        float sa, ca;
        __sincosf(base * (float)k, &sa, &ca);
        tw[k] = make_float2(ca, sa);
    }
    __syncthreads();

    for (int g = tid; g < T_LEN / 2; g += 512) {
        float2 a = s[2 * g], c = s[2 * g + 1];
        s[2 * g]     = make_float2(a.x + c.x, a.y + c.y);
        s[2 * g + 1] = make_float2(a.x - c.x, a.y - c.y);
    }
    __syncthreads();

    #pragma unroll
    for (int m = 4; m <= 1024; m *= 4) {
        int half = m >> 1;
        int tstep1 = T_LEN / m;
        int tstep2 = T_LEN / (2 * m);
        {
            int gidx = tid;   // T_LEN/4 = 512 butterflies, 1 per thread
            int blk = gidx / half;
            int j   = gidx - blk * half;
            int B   = blk * 2 * m;
            int p0 = B + j, p1 = p0 + half, p2 = p0 + m, p3 = p2 + half;
            float2 wA = tw[j * tstep1];
            float2 wB = tw[j * tstep2];
            float2 u0 = s[p0], u1 = s[p1], u2 = s[p2], u3 = s[p3];
            float2 t1 = cmul(wA, u1);
            float2 a0 = make_float2(u0.x + t1.x, u0.y + t1.y);
            float2 a1 = make_float2(u0.x - t1.x, u0.y - t1.y);
            float2 t3 = cmul(wA, u3);
            float2 a2 = make_float2(u2.x + t3.x, u2.y + t3.y);
            float2 a3 = make_float2(u2.x - t3.x, u2.y - t3.y);
            float2 t2 = cmul(wB, a2);
            float2 t4 = cmul(wB, a3);
            t4 = make_float2(t4.y, -t4.x);
            s[p0] = make_float2(a0.x + t2.x, a0.y + t2.y);
            s[p2] = make_float2(a0.x - t2.x, a0.y - t2.y);
            s[p1] = make_float2(a1.x + t4.x, a1.y + t4.y);
            s[p3] = make_float2(a1.x - t4.x, a1.y - t4.y);
        }
        __syncthreads();
    }

    for (int k = 1 + tid; k <= NBINS; k += 512) {
        float2 v = s[k];
        g_partial[(size_t)(k - 1) * NB + b] = sqrtf(v.x * v.x + v.y * v.y);
    }
}

__global__ void reduce_amp_kernel() {
    int k = blockIdx.x * blockDim.x + threadIdx.x;
    if (k >= NBINS) return;
    const float4* p = (const float4*)&g_partial[(size_t)k * NB];
    float acc = 0.f;
    #pragma unroll 8
    for (int i = 0; i < NB / 4; i++) {
        float4 v = p[i];
        acc += v.x + v.y + v.z + v.w;
    }
    g_amp[k] = acc * (1.f / (float)NB);
}

// ---------------------------------------------------------------------------
// 2) prep: weight packs + single-pass top-2 + per-period meta
// ---------------------------------------------------------------------------
struct Top2 { float v1; int i1; float v2; int i2; };

__device__ __forceinline__ bool t2gt(float av, int ai, float bv, int bi) {
    return av > bv || (av == bv && ai < bi);
}
__device__ __forceinline__ Top2 t2merge(Top2 a, Top2 b) {
    Top2 r;
    if (t2gt(a.v1, a.i1, b.v1, b.i1)) {
        r.v1 = a.v1; r.i1 = a.i1;
        if (t2gt(a.v2, a.i2, b.v1, b.i1)) { r.v2 = a.v2; r.i2 = a.i2; }
        else                              { r.v2 = b.v1; r.i2 = b.i1; }
    } else {
        r.v1 = b.v1; r.i1 = b.i1;
        if (t2gt(b.v2, b.i2, a.v1, a.i1)) { r.v2 = b.v2; r.i2 = b.i2; }
        else                              { r.v2 = a.v1; r.i2 = a.i1; }
    }
    return r;
}

__global__ void prep_kernel(const float* __restrict__ w1,
                            const float* __restrict__ w2,
                            const float* __restrict__ b1) {
    __shared__ Top2 warpRes[32];
    int tid = threadIdx.x;   // 1024

    const int NP = DMOD / 2;
    for (int idx = tid; idx < 2 * 2 * NP * 9; idx += 1024) {
        int orient = idx / (2 * NP * 9);
        int rem    = idx - orient * 2 * NP * 9;
        int layer  = rem / (NP * 9);
        int i      = rem - layer * NP * 9;
        int p = i / 9, s = i - p * 9;
        int g = s / 3, di = s % 3 - 1;
        int do_ = (g == 0) ? 0 : (g == 1 ? 1 : -1);
        int off = orient ? ((do_ + 1) * 3 + (di + 1)) : ((di + 1) * 3 + (do_ + 1));
        const float* w = layer ? w2 : w1;
        g_wq[orient][layer][i] = make_float2(w[(2 * p) * 9 + off], w[(2 * p + 1) * 9 + off]);
    }
    if (tid < NP) g_b1q[tid] = make_float2(b1[2 * tid], b1[2 * tid + 1]);

    // single-pass top-2
    Top2 t;
    t.v1 = g_amp[tid]; t.i1 = tid; t.v2 = -1e30f; t.i2 = 0x7FFFFFFF;
    #pragma unroll
    for (int off = 16; off >= 1; off >>= 1) {
        Top2 o;
        o.v1 = __shfl_xor_sync(0xFFFFFFFFu, t.v1, off);
        o.i1 = __shfl_xor_sync(0xFFFFFFFFu, t.i1, off);
        o.v2 = __shfl_xor_sync(0xFFFFFFFFu, t.v2, off);
        o.i2 = __shfl_xor_sync(0xFFFFFFFFu, t.i2, off);
        t = t2merge(t, o);
    }
    if ((tid & 31) == 0) warpRes[tid >> 5] = t;
    __syncthreads();

    if (tid < 32) {
        t = warpRes[tid];
        #pragma unroll
        for (int off = 16; off >= 1; off >>= 1) {
            Top2 o;
            o.v1 = __shfl_xor_sync(0xFFFFFFFFu, t.v1, off);
            o.i1 = __shfl_xor_sync(0xFFFFFFFFu, t.i1, off);
            o.v2 = __shfl_xor_sync(0xFFFFFFFFu, t.v2, off);
            o.i2 = __shfl_xor_sync(0xFFFFFFFFu, t.i2, off);
            t = t2merge(t, o);
        }
        if (tid == 0) {
            float e2 = __expf(t.v2 - t.v1);
            float inv = 1.f / (1.f + e2);
            float wgts[2] = { inv, e2 * inv };
            int   idxs[2] = { t.i1, t.i2 };
            for (int tt = 0; tt < 2; tt++) {
                int f = idxs[tt] + 1;
                int P = (int)llrint((double)T_LEN / (double)f); if (P < 1) P = 1;
                int cols = (T_LEN + P - 1) / P;
                int orient = (P <= cols) ? 0 : 1;
                int inner = orient ? cols : P;
                int outer = orient ? P : cols;
                int S = (inner + 2 + 3) & ~3;
                PMeta pm;
                pm.S = S; pm.padL = outer * S;
                pm.inner = inner; pm.outer = outer;
                pm.stepO = orient ? 1 : P;
                pm.stepI = orient ? P : 1;
                pm.orient = orient;
                pm.magic = 0xFFFFFFFFu / (unsigned)S + 1u;
                pm.wgt = wgts[tt];
                g_pm[tt] = pm;
            }
        }
    }
}

__device__ __forceinline__ ull gelu2(ull vq, ull C0, ull C1, ull HALF) {
    ull v2q = mul2(vq, vq);
    ull uq  = mul2(vq, fma2(C1, v2q, C0));
    float ul, uh;
    unpack2(uq, ul, uh);
    float tl, th;
    asm("tanh.approx.f32 %0, %1;" : "=f"(tl) : "f"(ul));
    asm("tanh.approx.f32 %0, %1;" : "=f"(th) : "f"(uh));
    ull tq = pack2(tl, th);
    return mul2(vq, fma2(HALF, tq, HALF));
}

// ---------------------------------------------------------------------------
// 3) f32x2 channel-paired register-resident fused conv (unchanged from R12)
// ---------------------------------------------------------------------------
__global__ __launch_bounds__(256, 2) void conv_kernel(
        const float* __restrict__ x,
        const float* __restrict__ b2) {
    const int period = blockIdx.z;
    const PMeta pm = g_pm[period];
    const int S = pm.S, inner = pm.inner, padL = pm.padL;
    const int stepO = pm.stepO, stepI = pm.stepI;
    const unsigned M = pm.magic;

    if (blockIdx.x * OUTSPAN >= padL) return;
    const int qb  = blockIdx.x * OUTSPAN - 48;
    const int b   = blockIdx.y;
    const int tid = threadIdx.x;

    __shared__ float xs[XLEN2];
    __shared__ float sUm[USPAN];
    __shared__ float sUp[USPAN];
    __shared__ __align__(16) ull w1s[(DMOD/2) * 9];
    __shared__ __align__(16) ull w2s[(DMOD/2) * 9];
    __shared__ ull b1s[DMOD / 2];
    __shared__ float b2s_s;

    {
        const ull* gw1 = (const ull*)g_wq[pm.orient][0];
        const ull* gw2 = (const ull*)g_wq[pm.orient][1];
        for (int i = tid; i < (DMOD/2) * 9; i += 256) {
            w1s[i] = gw1[i];
            w2s[i] = gw2[i];
        }
        if (tid < DMOD / 2) b1s[tid] = ((const ull*)g_b1q)[tid];
        if (tid == 0) b2s_s = b2[0];
    }

    const float* xb = x + (size_t)b * T_LEN;
    for (int i = tid; i < XLEN2; i += 256) {
        int q = qb - 52 + i;
        float v = 0.f;
        if (q >= 0 && q < padL) {
            unsigned o = mdiv((unsigned)q, M);
            int i_ = q - (int)o * S - 1;
            if (i_ >= 0 && i_ < inner) {
                int n = (int)o * stepO + i_ * stepI;
                if (n < T_LEN) v = xb[n];
            }
        }
        xs[i] = v;
    }
    __syncthreads();

    ull T0[8], T1[8], T2[8];
    {
        const float* xr = xs + tid * 4 + 50;
        #pragma unroll
        for (int k = 0; k < 8; k++) {
            T1[k] = bcast2(xr[k]);
            T2[k] = bcast2(xr[S + k]);
            T0[k] = bcast2(xr[-S + k]);
        }
    }

    ull Mq[6];
    #pragma unroll
    for (int t = 0; t < 6; t++) {
        int q = qb + tid * 4 - 1 + t;
        bool v = false;
        if (q >= 0 && q < padL) {
            unsigned o = mdiv((unsigned)q, M);
            int i_ = q - (int)o * S - 1;
            v = (i_ >= 0 && i_ < inner);
        }
        Mq[t] = bcast2(v ? 1.f : 0.f);
    }
    int on[4]; bool ov[4]; bool anyv = false;
    #pragma unroll
    for (int r = 0; r < 4; r++) {
        int lj = tid * 4 + r;
        int q  = qb + lj;
        ov[r] = false; on[r] = 0;
        if (lj >= 48 && lj < 48 + OUTSPAN && q < padL) {
            unsigned o = mdiv((unsigned)q, M);
            int i_ = q - (int)o * S - 1;
            if (i_ >= 0 && i_ < inner) {
                int n = (int)o * stepO + i_ * stepI;
                if (n < T_LEN) { ov[r] = true; on[r] = n; anyv = true; }
            }
        }
    }

    const ull C0   = bcast2(0.7978845608f);
    const ull C1   = bcast2(0.035677408136f);
    const ull HALF = bcast2(0.5f);

    ull U0q[4], Upq[4], Umq[4];
    #pragma unroll
    for (int r = 0; r < 4; r++) { U0q[r] = 0ull; Upq[r] = 0ull; Umq[r] = 0ull; }

    for (int pch = 0; pch < DMOD / 2; pch++) {
        const ull* w1r = &w1s[pch * 9];
        const ull* w2r = &w2s[pch * 9];
        ull bq = b1s[pch];
        ull hq[6];
        #pragma unroll
        for (int t = 0; t < 6; t++) {
            ull a = bq;
            a = fma2(w1r[0], T1[t],     a);
            a = fma2(w1r[1], T1[t + 1], a);
            a = fma2(w1r[2], T1[t + 2], a);
            a = fma2(w1r[3], T2[t],     a);
            a = fma2(w1r[4], T2[t + 1], a);
            a = fma2(w1r[5], T2[t + 2], a);
            a = fma2(w1r[6], T0[t],     a);
            a = fma2(w1r[7], T0[t + 1], a);
            a = fma2(w1r[8], T0[t + 2], a);
            hq[t] = mul2(gelu2(a, C0, C1, HALF), Mq[t]);
        }
        #pragma unroll
        for (int r = 0; r < 4; r++) {
            U0q[r] = fma2(w2r[0], hq[r],     U0q[r]);
            U0q[r] = fma2(w2r[1], hq[r + 1], U0q[r]);
            U0q[r] = fma2(w2r[2], hq[r + 2], U0q[r]);
            Upq[r] = fma2(w2r[3], hq[r],     Upq[r]);
            Upq[r] = fma2(w2r[4], hq[r + 1], Upq[r]);
            Upq[r] = fma2(w2r[5], hq[r + 2], Upq[r]);
            Umq[r] = fma2(w2r[6], hq[r],     Umq[r]);
            Umq[r] = fma2(w2r[7], hq[r + 1], Umq[r]);
            Umq[r] = fma2(w2r[8], hq[r + 2], Umq[r]);
        }
    }

    float U0[4], Um[4], Up[4];
    #pragma unroll
    for (int r = 0; r < 4; r++) {
        float lo, hi;
        unpack2(U0q[r], lo, hi); U0[r] = lo + hi;
        unpack2(Upq[r], lo, hi); Up[r] = lo + hi;
        unpack2(Umq[r], lo, hi); Um[r] = lo + hi;
    }
    *(float4*)(sUm + tid * 4) = make_float4(Um[0], Um[1], Um[2], Um[3]);
    *(float4*)(sUp + tid * 4) = make_float4(Up[0], Up[1], Up[2], Up[3]);
    __syncthreads();

    if (anyv) {
        float* yout = g_y2[period] + (size_t)b * T_LEN;
        #pragma unroll
        for (int r = 0; r < 4; r++) {
            if (ov[r]) {
                int lj = tid * 4 + r;
                float val = b2s_s + U0[r] + sUm[lj - S] + sUp[lj + S];
                yout[on[r]] = pm.wgt * val;
            }
        }
    }
}

// ---------------------------------------------------------------------------
// 4) Head GEMM, split-K=8, f32x2 inner
// ---------------------------------------------------------------------------
#define GBM 64
#define GBN 64
#define GBK 32
__global__ __launch_bounds__(256) void head_gemm_kernel(
        const float* __restrict__ hw) {
    __shared__ __align__(16) float As[GBK][GBM];
    __shared__ __align__(16) float Bs[GBK][GBN];
    const int tid = threadIdx.x;
    const int n0 = blockIdx.x * GBN, m0 = blockIdx.y * GBM;
    const int kz = blockIdx.z;
    const int ty = tid / 16, tx = tid % 16;
    const int tm = ty * 4, tn = tx * 4;

    const float* y0 = g_y2[0];
    const float* y1 = g_y2[1];

    ull acc2[4][2];
    #pragma unroll
    for (int i = 0; i < 4; i++) { acc2[i][0] = 0ull; acc2[i][1] = 0ull; }

    const int kbase = kz * KSEG;
    for (int k0 = kbase; k0 < kbase + KSEG; k0 += GBK) {
        #pragma unroll
        for (int i = tid; i < GBM * GBK; i += 256) {
            int m = i / GBK, k = i % GBK;
            size_t off = (size_t)(m0 + m) * T_LEN + k0 + k;
            As[k][m] = y0[off] + y1[off];
        }
        #pragma unroll
        for (int i = tid; i < GBN * GBK; i += 256) {
            int n = i / GBK, k = i % GBK;
            Bs[k][n] = (n0 + n < H_OUT) ? hw[(size_t)(n0 + n) * T_LEN + k0 + k] : 0.f;
        }
        __syncthreads();
        #pragma unroll
        for (int k = 0; k < GBK; k++) {
            float4 a4 = *(const float4*)&As[k][tm];
            float4 b4 = *(const float4*)&Bs[k][tn];
            ull bq0 = pack2(b4.x, b4.y);
            ull bq1 = pack2(b4.z, b4.w);
            float av[4] = {a4.x, a4.y, a4.z, a4.w};
            #pragma unroll
            for (int i = 0; i < 4; i++) {
                ull ai = bcast2(av[i]);
                acc2[i][0] = fma2(ai, bq0, acc2[i][0]);
                acc2[i][1] = fma2(ai, bq1, acc2[i][1]);
            }
        }
        __syncthreads();
    }
    float* outp = g_hp[kz];
    #pragma unroll
    for (int i = 0; i < 4; i++) {
        int m = m0 + tm + i;
        float v0, v1v, v2, v3;
        unpack2(acc2[i][0], v0, v1v);
        unpack2(acc2[i][1], v2, v3);
        float vals[4] = {v0, v1v, v2, v3};
        #pragma unroll
        for (int j = 0; j < 4; j++) {
            int n = n0 + tn + j;
            if (n < H_OUT) outp[(size_t)m * H_OUT + n] = vals[j];
        }
    }
}

__global__ void head_epilogue_kernel(const float* __restrict__ hb,
                                     float* __restrict__ out) {
    int idx4 = blockIdx.x * blockDim.x + threadIdx.x;
    if (idx4 >= NB * H_OUT / 4) return;
    int base = idx4 * 4;
    int n = base % H_OUT;                 // 720 % 4 == 0 -> aligned
    float4 v = *(const float4*)&hb[n];
    #pragma unroll
    for (int kz = 0; kz < KSPLIT; kz++) {
        float4 p = *(const float4*)&g_hp[kz][base];
        v.x += p.x; v.y += p.y; v.z += p.z; v.w += p.w;
    }
    *(float4*)&out[base] = v;
}

// ---------------------------------------------------------------------------
extern "C" void kernel_launch(void* const* d_in, const int* in_sizes, int n_in,
                              void* d_out, int out_size) {
    const float* x  = (const float*)d_in[0];
    const float* w1 = (const float*)d_in[1];
    const float* b1 = (const float*)d_in[2];
    const float* w2 = (const float*)d_in[3];
    const float* b2 = (const float*)d_in[4];
    const float* hw = (const float*)d_in[5];
    const float* hb = (const float*)d_in[6];
    float* out = (float*)d_out;

    fft_kernel<<<NB, 512>>>(x);
    reduce_amp_kernel<<<NBINS / 256, 256>>>();
    prep_kernel<<<1, NBINS>>>(w1, w2, b1);
    conv_kernel<<<dim3(NCONVBLK, NB, 2), 256>>>(x, b2);
    head_gemm_kernel<<<dim3((H_OUT + GBN - 1) / GBN, NB / GBM, KSPLIT), 256>>>(hw);
    head_epilogue_kernel<<<(NB * H_OUT / 4 + 255) / 256, 256>>>(hb, out);
}

// round 14
// speedup vs baseline: 1.9502x; 1.0033x over previous
#include <cuda_runtime.h>
#include <math.h>

#define T_LEN 2048
#define NB    256
#define DMOD  64
#define H_OUT 720
#define NBINS 1024
#define NH    1024            // half-size complex FFT
#define OUTSPAN 928
#define USPAN  1024
#define XLEN2  1136
#define NCONVBLK 9
#define KSPLIT 8
#define KSEG  (T_LEN / KSPLIT)

typedef unsigned long long ull;

struct PMeta {
    int S, padL, inner, outer, stepO, stepI, orient;
    unsigned magic;
    float wgt;
};
__device__ PMeta g_pm[2];
__device__ float g_amp[NBINS];
__device__ float g_partial[NBINS * NB];
__device__ float2 g_wq[2][2][(DMOD/2) * 9];
__device__ float2 g_b1q[DMOD / 2];
__device__ float g_y2[2][NB * T_LEN];
__device__ float g_hp[KSPLIT][NB * H_OUT];

__device__ __forceinline__ unsigned mdiv(unsigned q, unsigned M) {
    return (unsigned)(((unsigned long long)q * M) >> 32);
}
__device__ __forceinline__ float2 cmul(float2 a, float2 b) {
    return make_float2(a.x * b.x - a.y * b.y, a.x * b.y + a.y * b.x);
}

// ---- f32x2 packed helpers ----
__device__ __forceinline__ ull pack2(float lo, float hi) {
    ull r; asm("mov.b64 %0, {%1, %2};" : "=l"(r) : "f"(lo), "f"(hi)); return r;
}
__device__ __forceinline__ ull bcast2(float v) { return pack2(v, v); }
__device__ __forceinline__ void unpack2(ull v, float& lo, float& hi) {
    asm("mov.b64 {%0, %1}, %2;" : "=f"(lo), "=f"(hi) : "l"(v));
}
__device__ __forceinline__ ull fma2(ull a, ull b, ull c) {
    ull d; asm("fma.rn.f32x2 %0, %1, %2, %3;" : "=l"(d) : "l"(a), "l"(b), "l"(c)); return d;
}
__device__ __forceinline__ ull mul2(ull a, ull b) {
    ull d; asm("mul.rn.f32x2 %0, %1, %2;" : "=l"(d) : "l"(a), "l"(b)); return d;
}
__device__ __forceinline__ ull add2(ull a, ull b) {
    ull d; asm("add.rn.f32x2 %0, %1, %2;" : "=l"(d) : "l"(a), "l"(b)); return d;
}

// ---------------------------------------------------------------------------
// 1) Real-input FFT: pack to 1024 complex, radix-2^2 FFT, conj-symmetry unpack
// ---------------------------------------------------------------------------
__global__ __launch_bounds__(512) void fft_kernel(const float* __restrict__ x) {
    __shared__ float2 s[NH];
    __shared__ float2 tw[NH / 2];
    int b = blockIdx.x, tid = threadIdx.x;
    const float* xb = x + (size_t)b * T_LEN;

    // pack z[n] = x[2n] + i x[2n+1], 10-bit bit-reversed
    for (int i = tid; i < NH; i += 512) {
        int rev = __brev((unsigned)i) >> 22;
        const float2 v = *(const float2*)(xb + 2 * i);
        s[rev] = v;
    }
    const float base = -6.283185307179586f / (float)NH;
    if (tid < NH / 2) {
        float sa, ca;
        __sincosf(base * (float)tid, &sa, &ca);
        tw[tid] = make_float2(ca, sa);
    }
    __syncthreads();

    // stage m=2 (512 butterflies, 1/thread)
    {
        int g = tid;
        float2 a = s[2 * g], c = s[2 * g + 1];
        s[2 * g]     = make_float2(a.x + c.x, a.y + c.y);
        s[2 * g + 1] = make_float2(a.x - c.x, a.y - c.y);
    }
    __syncthreads();

    // fused stage pairs m = 4, 16, 64, 256  (256 butterflies each)
    #pragma unroll
    for (int m = 4; m <= 256; m *= 4) {
        if (tid < NH / 4) {
            int half = m >> 1;
            int tstep1 = NH / m;
            int tstep2 = NH / (2 * m);
            int gidx = tid;
            int blk = gidx / half;
            int j   = gidx - blk * half;
            int B   = blk * 2 * m;
            int p0 = B + j, p1 = p0 + half, p2 = p0 + m, p3 = p2 + half;
            float2 wA = tw[j * tstep1];
            float2 wB = tw[j * tstep2];
            float2 u0 = s[p0], u1 = s[p1], u2 = s[p2], u3 = s[p3];
            float2 t1 = cmul(wA, u1);
            float2 a0 = make_float2(u0.x + t1.x, u0.y + t1.y);
            float2 a1 = make_float2(u0.x - t1.x, u0.y - t1.y);
            float2 t3 = cmul(wA, u3);
            float2 a2 = make_float2(u2.x + t3.x, u2.y + t3.y);
            float2 a3 = make_float2(u2.x - t3.x, u2.y - t3.y);
            float2 t2 = cmul(wB, a2);
            float2 t4 = cmul(wB, a3);
            t4 = make_float2(t4.y, -t4.x);
            s[p0] = make_float2(a0.x + t2.x, a0.y + t2.y);
            s[p2] = make_float2(a0.x - t2.x, a0.y - t2.y);
            s[p1] = make_float2(a1.x + t4.x, a1.y + t4.y);
            s[p3] = make_float2(a1.x - t4.x, a1.y - t4.y);
        }
        __syncthreads();
    }

    // final radix-2 stage m=1024 (512 butterflies, 1/thread)
    {
        int j = tid;                       // 0..511
        float2 w = tw[j];
        float2 u = s[j], v = s[j + NH / 2];
        float2 t = cmul(w, v);
        s[j]          = make_float2(u.x + t.x, u.y + t.y);
        s[j + NH / 2] = make_float2(u.x - t.x, u.y - t.y);
    }
    __syncthreads();

    // unpack: X[k] = A + W_2048^k * B, k = 1..1023 ; X[1024] = ReZ0 - ImZ0
    const float ubase = -6.283185307179586f / (float)T_LEN;
    for (int k = 1 + tid; k < NH; k += 512) {
        float2 Zk = s[k];
        float2 Zm = s[NH - k];
        float2 A = make_float2(0.5f * (Zk.x + Zm.x), 0.5f * (Zk.y - Zm.y));
        float2 B = make_float2(0.5f * (Zk.y + Zm.y), -0.5f * (Zk.x - Zm.x));
        float sn, cs;
        __sincosf(ubase * (float)k, &sn, &cs);
        float Xr = A.x + cs * B.x - sn * B.y;
        float Xi = A.y + cs * B.y + sn * B.x;
        g_partial[(size_t)(k - 1) * NB + b] = sqrtf(Xr * Xr + Xi * Xi);
    }
    if (tid == 0) {
        float2 Z0 = s[0];
        g_partial[(size_t)(NH - 1) * NB + b] = fabsf(Z0.x - Z0.y);
    }
}

__global__ void reduce_amp_kernel() {
    int k = blockIdx.x * blockDim.x + threadIdx.x;
    if (k >= NBINS) return;
    const float4* p = (const float4*)&g_partial[(size_t)k * NB];
    float acc = 0.f;
    #pragma unroll 8
    for (int i = 0; i < NB / 4; i++) {
        float4 v = p[i];
        acc += v.x + v.y + v.z + v.w;
    }
    g_amp[k] = acc * (1.f / (float)NB);
}

// ---------------------------------------------------------------------------
// 2) prep: weight packs + single-pass top-2 + per-period meta
// ---------------------------------------------------------------------------
struct Top2 { float v1; int i1; float v2; int i2; };

__device__ __forceinline__ bool t2gt(float av, int ai, float bv, int bi) {
    return av > bv || (av == bv && ai < bi);
}
__device__ __forceinline__ Top2 t2merge(Top2 a, Top2 b) {
    Top2 r;
    if (t2gt(a.v1, a.i1, b.v1, b.i1)) {
        r.v1 = a.v1; r.i1 = a.i1;
        if (t2gt(a.v2, a.i2, b.v1, b.i1)) { r.v2 = a.v2; r.i2 = a.i2; }
        else                              { r.v2 = b.v1; r.i2 = b.i1; }
    } else {
        r.v1 = b.v1; r.i1 = b.i1;
        if (t2gt(b.v2, b.i2, a.v1, a.i1)) { r.v2 = b.v2; r.i2 = b.i2; }
        else                              { r.v2 = a.v1; r.i2 = a.i1; }
    }
    return r;
}

__global__ void prep_kernel(const float* __restrict__ w1,
                            const float* __restrict__ w2,
                            const float* __restrict__ b1) {
    __shared__ Top2 warpRes[32];
    int tid = threadIdx.x;   // 1024

    const int NP = DMOD / 2;
    for (int idx = tid; idx < 2 * 2 * NP * 9; idx += 1024) {
        int orient = idx / (2 * NP * 9);
        int rem    = idx - orient * 2 * NP * 9;
        int layer  = rem / (NP * 9);
        int i      = rem - layer * NP * 9;
        int p = i / 9, s = i - p * 9;
        int g = s / 3, di = s % 3 - 1;
        int do_ = (g == 0) ? 0 : (g == 1 ? 1 : -1);
        int off = orient ? ((do_ + 1) * 3 + (di + 1)) : ((di + 1) * 3 + (do_ + 1));
        const float* w = layer ? w2 : w1;
        g_wq[orient][layer][i] = make_float2(w[(2 * p) * 9 + off], w[(2 * p + 1) * 9 + off]);
    }
    if (tid < NP) g_b1q[tid] = make_float2(b1[2 * tid], b1[2 * tid + 1]);

    Top2 t;
    t.v1 = g_amp[tid]; t.i1 = tid; t.v2 = -1e30f; t.i2 = 0x7FFFFFFF;
    #pragma unroll
    for (int off = 16; off >= 1; off >>= 1) {
        Top2 o;
        o.v1 = __shfl_xor_sync(0xFFFFFFFFu, t.v1, off);
        o.i1 = __shfl_xor_sync(0xFFFFFFFFu, t.i1, off);
        o.v2 = __shfl_xor_sync(0xFFFFFFFFu, t.v2, off);
        o.i2 = __shfl_xor_sync(0xFFFFFFFFu, t.i2, off);
        t = t2merge(t, o);
    }
    if ((tid & 31) == 0) warpRes[tid >> 5] = t;
    __syncthreads();

    if (tid < 32) {
        t = warpRes[tid];
        #pragma unroll
        for (int off = 16; off >= 1; off >>= 1) {
            Top2 o;
            o.v1 = __shfl_xor_sync(0xFFFFFFFFu, t.v1, off);
            o.i1 = __shfl_xor_sync(0xFFFFFFFFu, t.i1, off);
            o.v2 = __shfl_xor_sync(0xFFFFFFFFu, t.v2, off);
            o.i2 = __shfl_xor_sync(0xFFFFFFFFu, t.i2, off);
            t = t2merge(t, o);
        }
        if (tid == 0) {
            float e2 = __expf(t.v2 - t.v1);
            float inv = 1.f / (1.f + e2);
            float wgts[2] = { inv, e2 * inv };
            int   idxs[2] = { t.i1, t.i2 };
            for (int tt = 0; tt < 2; tt++) {
                int f = idxs[tt] + 1;
                int P = (int)llrint((double)T_LEN / (double)f); if (P < 1) P = 1;
                int cols = (T_LEN + P - 1) / P;
                int orient = (P <= cols) ? 0 : 1;
                int inner = orient ? cols : P;
                int outer = orient ? P : cols;
                int S = (inner + 2 + 3) & ~3;
                PMeta pm;
                pm.S = S; pm.padL = outer * S;
                pm.inner = inner; pm.outer = outer;
                pm.stepO = orient ? 1 : P;
                pm.stepI = orient ? P : 1;
                pm.orient = orient;
                pm.magic = 0xFFFFFFFFu / (unsigned)S + 1u;
                pm.wgt = wgts[tt];
                g_pm[tt] = pm;
            }
        }
    }
}

__device__ __forceinline__ ull gelu2(ull vq, ull C0, ull C1, ull HALF) {
    ull v2q = mul2(vq, vq);
    ull uq  = mul2(vq, fma2(C1, v2q, C0));
    float ul, uh;
    unpack2(uq, ul, uh);
    float tl, th;
    asm("tanh.approx.f32 %0, %1;" : "=f"(tl) : "f"(ul));
    asm("tanh.approx.f32 %0, %1;" : "=f"(th) : "f"(uh));
    ull tq = pack2(tl, th);
    return mul2(vq, fma2(HALF, tq, HALF));
}

// ---------------------------------------------------------------------------
// 3) f32x2 channel-paired register-resident fused conv (split h chains)
// ---------------------------------------------------------------------------
__global__ __launch_bounds__(256, 2) void conv_kernel(
        const float* __restrict__ x,
        const float* __restrict__ b2) {
    const int period = blockIdx.z;
    const PMeta pm = g_pm[period];
    const int S = pm.S, inner = pm.inner, padL = pm.padL;
    const int stepO = pm.stepO, stepI = pm.stepI;
    const unsigned M = pm.magic;

    if (blockIdx.x * OUTSPAN >= padL) return;
    const int qb  = blockIdx.x * OUTSPAN - 48;
    const int b   = blockIdx.y;
    const int tid = threadIdx.x;

    __shared__ float xs[XLEN2];
    __shared__ float sUm[USPAN];
    __shared__ float sUp[USPAN];
    __shared__ __align__(16) ull w1s[(DMOD/2) * 9];
    __shared__ __align__(16) ull w2s[(DMOD/2) * 9];
    __shared__ ull b1s[DMOD / 2];
    __shared__ float b2s_s;

    {
        const ull* gw1 = (const ull*)g_wq[pm.orient][0];
        const ull* gw2 = (const ull*)g_wq[pm.orient][1];
        for (int i = tid; i < (DMOD/2) * 9; i += 256) {
            w1s[i] = gw1[i];
            w2s[i] = gw2[i];
        }
        if (tid < DMOD / 2) b1s[tid] = ((const ull*)g_b1q)[tid];
        if (tid == 0) b2s_s = b2[0];
    }

    const float* xb = x + (size_t)b * T_LEN;
    for (int i = tid; i < XLEN2; i += 256) {
        int q = qb - 52 + i;
        float v = 0.f;
        if (q >= 0 && q < padL) {
            unsigned o = mdiv((unsigned)q, M);
            int i_ = q - (int)o * S - 1;
            if (i_ >= 0 && i_ < inner) {
                int n = (int)o * stepO + i_ * stepI;
                if (n < T_LEN) v = xb[n];
            }
        }
        xs[i] = v;
    }
    __syncthreads();

    ull T0[8], T1[8], T2[8];
    {
        const float* xr = xs + tid * 4 + 50;
        #pragma unroll
        for (int k = 0; k < 8; k++) {
            T1[k] = bcast2(xr[k]);
            T2[k] = bcast2(xr[S + k]);
            T0[k] = bcast2(xr[-S + k]);
        }
    }

    ull Mq[6];
    #pragma unroll
    for (int t = 0; t < 6; t++) {
        int q = qb + tid * 4 - 1 + t;
        bool v = false;
        if (q >= 0 && q < padL) {
            unsigned o = mdiv((unsigned)q, M);
            int i_ = q - (int)o * S - 1;
            v = (i_ >= 0 && i_ < inner);
        }
        Mq[t] = bcast2(v ? 1.f : 0.f);
    }
    int on[4]; bool ov[4]; bool anyv = false;
    #pragma unroll
    for (int r = 0; r < 4; r++) {
        int lj = tid * 4 + r;
        int q  = qb + lj;
        ov[r] = false; on[r] = 0;
        if (lj >= 48 && lj < 48 + OUTSPAN && q < padL) {
            unsigned o = mdiv((unsigned)q, M);
            int i_ = q - (int)o * S - 1;
            if (i_ >= 0 && i_ < inner) {
                int n = (int)o * stepO + i_ * stepI;
                if (n < T_LEN) { ov[r] = true; on[r] = n; anyv = true; }
            }
        }
    }

    const ull C0   = bcast2(0.7978845608f);
    const ull C1   = bcast2(0.035677408136f);
    const ull HALF = bcast2(0.5f);

    ull U0q[4], Upq[4], Umq[4];
    #pragma unroll
    for (int r = 0; r < 4; r++) { U0q[r] = 0ull; Upq[r] = 0ull; Umq[r] = 0ull; }

    for (int pch = 0; pch < DMOD / 2; pch++) {
        const ull* w1r = &w1s[pch * 9];
        const ull* w2r = &w2s[pch * 9];
        ull bq = b1s[pch];
        ull hq[6];
        #pragma unroll
        for (int t = 0; t < 6; t++) {
            // two parallel chains (depth 5 / 4) + final add
            ull cA = fma2(w1r[0], T1[t],     bq);
            cA = fma2(w1r[3], T2[t],     cA);
            cA = fma2(w1r[6], T0[t],     cA);
            cA = fma2(w1r[1], T1[t + 1], cA);
            cA = fma2(w1r[4], T2[t + 1], cA);
            ull cB = mul2(w1r[7], T0[t + 1]);
            cB = fma2(w1r[2], T1[t + 2], cB);
            cB = fma2(w1r[5], T2[t + 2], cB);
            cB = fma2(w1r[8], T0[t + 2], cB);
            hq[t] = mul2(gelu2(add2(cA, cB), C0, C1, HALF), Mq[t]);
        }
        #pragma unroll
        for (int r = 0; r < 4; r++) {
            U0q[r] = fma2(w2r[0], hq[r],     U0q[r]);
            U0q[r] = fma2(w2r[1], hq[r + 1], U0q[r]);
            U0q[r] = fma2(w2r[2], hq[r + 2], U0q[r]);
            Upq[r] = fma2(w2r[3], hq[r],     Upq[r]);
            Upq[r] = fma2(w2r[4], hq[r + 1], Upq[r]);
            Upq[r] = fma2(w2r[5], hq[r + 2], Upq[r]);
            Umq[r] = fma2(w2r[6], hq[r],     Umq[r]);
            Umq[r] = fma2(w2r[7], hq[r + 1], Umq[r]);
            Umq[r] = fma2(w2r[8], hq[r + 2], Umq[r]);
        }
    }

    float U0[4], Um[4], Up[4];
    #pragma unroll
    for (int r = 0; r < 4; r++) {
        float lo, hi;
        unpack2(U0q[r], lo, hi); U0[r] = lo + hi;
        unpack2(Upq[r], lo, hi); Up[r] = lo + hi;
        unpack2(Umq[r], lo, hi); Um[r] = lo + hi;
    }
    *(float4*)(sUm + tid * 4) = make_float4(Um[0], Um[1], Um[2], Um[3]);
    *(float4*)(sUp + tid * 4) = make_float4(Up[0], Up[1], Up[2], Up[3]);
    __syncthreads();

    if (anyv) {
        float* yout = g_y2[period] + (size_t)b * T_LEN;
        #pragma unroll
        for (int r = 0; r < 4; r++) {
            if (ov[r]) {
                int lj = tid * 4 + r;
                float val = b2s_s + U0[r] + sUm[lj - S] + sUp[lj + S];
                yout[on[r]] = pm.wgt * val;
            }
        }
    }
}

// ---------------------------------------------------------------------------
// 4) Head GEMM, split-K=8, f32x2 inner
// ---------------------------------------------------------------------------
#define GBM 64
#define GBN 64
#define GBK 32
__global__ __launch_bounds__(256) void head_gemm_kernel(
        const float* __restrict__ hw) {
    __shared__ __align__(16) float As[GBK][GBM];
    __shared__ __align__(16) float Bs[GBK][GBN];
    const int tid = threadIdx.x;
    const int n0 = blockIdx.x * GBN, m0 = blockIdx.y * GBM;
    const int kz = blockIdx.z;
    const int ty = tid / 16, tx = tid % 16;
    const int tm = ty * 4, tn = tx * 4;

    const float* y0 = g_y2[0];
    const float* y1 = g_y2[1];

    ull acc2[4][2];
    #pragma unroll
    for (int i = 0; i < 4; i++) { acc2[i][0] = 0ull; acc2[i][1] = 0ull; }

    const int kbase = kz * KSEG;
    for (int k0 = kbase; k0 < kbase + KSEG; k0 += GBK) {
        #pragma unroll
        for (int i = tid; i < GBM * GBK; i += 256) {
            int m = i / GBK, k = i % GBK;
            size_t off = (size_t)(m0 + m) * T_LEN + k0 + k;
            As[k][m] = y0[off] + y1[off];
        }
        #pragma unroll
        for (int i = tid; i < GBN * GBK; i += 256) {
            int n = i / GBK, k = i % GBK;
            Bs[k][n] = (n0 + n < H_OUT) ? hw[(size_t)(n0 + n) * T_LEN + k0 + k] : 0.f;
        }
        __syncthreads();
        #pragma unroll
        for (int k = 0; k < GBK; k++) {
            float4 a4 = *(const float4*)&As[k][tm];
            float4 b4 = *(const float4*)&Bs[k][tn];
            ull bq0 = pack2(b4.x, b4.y);
            ull bq1 = pack2(b4.z, b4.w);
            float av[4] = {a4.x, a4.y, a4.z, a4.w};
            #pragma unroll
            for (int i = 0; i < 4; i++) {
                ull ai = bcast2(av[i]);
                acc2[i][0] = fma2(ai, bq0, acc2[i][0]);
                acc2[i][1] = fma2(ai, bq1, acc2[i][1]);
            }
        }
        __syncthreads();
    }
    float* outp = g_hp[kz];
    #pragma unroll
    for (int i = 0; i < 4; i++) {
        int m = m0 + tm + i;
        float v0, v1v, v2, v3;
        unpack2(acc2[i][0], v0, v1v);
        unpack2(acc2[i][1], v2, v3);
        float vals[4] = {v0, v1v, v2, v3};
        #pragma unroll
        for (int j = 0; j < 4; j++) {
            int n = n0 + tn + j;
            if (n < H_OUT) outp[(size_t)m * H_OUT + n] = vals[j];
        }
    }
}

__global__ void head_epilogue_kernel(const float* __restrict__ hb,
                                     float* __restrict__ out) {
    int idx4 = blockIdx.x * blockDim.x + threadIdx.x;
    if (idx4 >= NB * H_OUT / 4) return;
    int base = idx4 * 4;
    int n = base % H_OUT;
    float4 v = *(const float4*)&hb[n];
    #pragma unroll
    for (int kz = 0; kz < KSPLIT; kz++) {
        float4 p = *(const float4*)&g_hp[kz][base];
        v.x += p.x; v.y += p.y; v.z += p.z; v.w += p.w;
    }
    *(float4*)&out[base] = v;
}

// ---------------------------------------------------------------------------
extern "C" void kernel_launch(void* const* d_in, const int* in_sizes, int n_in,
                              void* d_out, int out_size) {
    const float* x  = (const float*)d_in[0];
    const float* w1 = (const float*)d_in[1];
    const float* b1 = (const float*)d_in[2];
    const float* w2 = (const float*)d_in[3];
    const float* b2 = (const float*)d_in[4];
    const float* hw = (const float*)d_in[5];
    const float* hb = (const float*)d_in[6];
    float* out = (float*)d_out;

    fft_kernel<<<NB, 512>>>(x);
    reduce_amp_kernel<<<NBINS / 256, 256>>>();
    prep_kernel<<<1, NBINS>>>(w1, w2, b1);
    conv_kernel<<<dim3(NCONVBLK, NB, 2), 256>>>(x, b2);
    head_gemm_kernel<<<dim3((H_OUT + GBN - 1) / GBN, NB / GBM, KSPLIT), 256>>>(hw);
    head_epilogue_kernel<<<(NB * H_OUT / 4 + 255) / 256, 256>>>(hb, out);
}

// round 15
// speedup vs baseline: 2.1372x; 1.0959x over previous
#include <cuda_runtime.h>
#include <math.h>

#define T_LEN 2048
#define NB    256
#define DMOD  64
#define H_OUT 720
#define NBINS 1024
#define NH    1024            // half-size complex FFT
#define OUTSPAN 928
#define USPAN  1024
#define XLEN2  1136
#define NCONVBLK 5            // ceil(max padL 4096 / 928)
#define KSPLIT 8
#define KSEG  (T_LEN / KSPLIT)

typedef unsigned long long ull;

struct PMeta {
    int S, padL, inner, outer, stepO, stepI, orient;
    unsigned magic;
    float wgt;
};
__device__ PMeta g_pm[2];
__device__ float g_amp[NBINS];
__device__ float g_partial[NBINS * NB];
__device__ float2 g_wq[2][2][(DMOD/2) * 9];
__device__ float2 g_b1q[DMOD / 2];
__device__ float g_y2[2][NB * T_LEN];
__device__ float g_hp[KSPLIT][NB * H_OUT];

__device__ __forceinline__ unsigned mdiv(unsigned q, unsigned M) {
    return (unsigned)(((unsigned long long)q * M) >> 32);
}
__device__ __forceinline__ float2 cmul(float2 a, float2 b) {
    return make_float2(a.x * b.x - a.y * b.y, a.x * b.y + a.y * b.x);
}

// ---- f32x2 packed helpers ----
__device__ __forceinline__ ull pack2(float lo, float hi) {
    ull r; asm("mov.b64 %0, {%1, %2};" : "=l"(r) : "f"(lo), "f"(hi)); return r;
}
__device__ __forceinline__ ull bcast2(float v) { return pack2(v, v); }
__device__ __forceinline__ void unpack2(ull v, float& lo, float& hi) {
    asm("mov.b64 {%0, %1}, %2;" : "=f"(lo), "=f"(hi) : "l"(v));
}
__device__ __forceinline__ ull fma2(ull a, ull b, ull c) {
    ull d; asm("fma.rn.f32x2 %0, %1, %2, %3;" : "=l"(d) : "l"(a), "l"(b), "l"(c)); return d;
}
__device__ __forceinline__ ull mul2(ull a, ull b) {
    ull d; asm("mul.rn.f32x2 %0, %1, %2;" : "=l"(d) : "l"(a), "l"(b)); return d;
}

// ---------------------------------------------------------------------------
// 1) Real-input FFT: pack to 1024 complex, radix-2^2 FFT, conj-symmetry unpack
// ---------------------------------------------------------------------------
__global__ __launch_bounds__(512) void fft_kernel(const float* __restrict__ x) {
    __shared__ float2 s[NH];
    __shared__ float2 tw[NH / 2];
    int b = blockIdx.x, tid = threadIdx.x;
    const float* xb = x + (size_t)b * T_LEN;

    for (int i = tid; i < NH; i += 512) {
        int rev = __brev((unsigned)i) >> 22;
        const float2 v = *(const float2*)(xb + 2 * i);
        s[rev] = v;
    }
    const float base = -6.283185307179586f / (float)NH;
    if (tid < NH / 2) {
        float sa, ca;
        __sincosf(base * (float)tid, &sa, &ca);
        tw[tid] = make_float2(ca, sa);
    }
    __syncthreads();

    {
        int g = tid;
        float2 a = s[2 * g], c = s[2 * g + 1];
        s[2 * g]     = make_float2(a.x + c.x, a.y + c.y);
        s[2 * g + 1] = make_float2(a.x - c.x, a.y - c.y);
    }
    __syncthreads();

    #pragma unroll
    for (int m = 4; m <= 256; m *= 4) {
        if (tid < NH / 4) {
            int half = m >> 1;
            int tstep1 = NH / m;
            int tstep2 = NH / (2 * m);
            int gidx = tid;
            int blk = gidx / half;
            int j   = gidx - blk * half;
            int B   = blk * 2 * m;
            int p0 = B + j, p1 = p0 + half, p2 = p0 + m, p3 = p2 + half;
            float2 wA = tw[j * tstep1];
            float2 wB = tw[j * tstep2];
            float2 u0 = s[p0], u1 = s[p1], u2 = s[p2], u3 = s[p3];
            float2 t1 = cmul(wA, u1);
            float2 a0 = make_float2(u0.x + t1.x, u0.y + t1.y);
            float2 a1 = make_float2(u0.x - t1.x, u0.y - t1.y);
            float2 t3 = cmul(wA, u3);
            float2 a2 = make_float2(u2.x + t3.x, u2.y + t3.y);
            float2 a3 = make_float2(u2.x - t3.x, u2.y - t3.y);
            float2 t2 = cmul(wB, a2);
            float2 t4 = cmul(wB, a3);
            t4 = make_float2(t4.y, -t4.x);
            s[p0] = make_float2(a0.x + t2.x, a0.y + t2.y);
            s[p2] = make_float2(a0.x - t2.x, a0.y - t2.y);
            s[p1] = make_float2(a1.x + t4.x, a1.y + t4.y);
            s[p3] = make_float2(a1.x - t4.x, a1.y - t4.y);
        }
        __syncthreads();
    }

    {
        int j = tid;
        float2 w = tw[j];
        float2 u = s[j], v = s[j + NH / 2];
        float2 t = cmul(w, v);
        s[j]          = make_float2(u.x + t.x, u.y + t.y);
        s[j + NH / 2] = make_float2(u.x - t.x, u.y - t.y);
    }
    __syncthreads();

    const float ubase = -6.283185307179586f / (float)T_LEN;
    for (int k = 1 + tid; k < NH; k += 512) {
        float2 Zk = s[k];
        float2 Zm = s[NH - k];
        float2 A = make_float2(0.5f * (Zk.x + Zm.x), 0.5f * (Zk.y - Zm.y));
        float2 B = make_float2(0.5f * (Zk.y + Zm.y), -0.5f * (Zk.x - Zm.x));
        float sn, cs;
        __sincosf(ubase * (float)k, &sn, &cs);
        float Xr = A.x + cs * B.x - sn * B.y;
        float Xi = A.y + cs * B.y + sn * B.x;
        g_partial[(size_t)(k - 1) * NB + b] = sqrtf(Xr * Xr + Xi * Xi);
    }
    if (tid == 0) {
        float2 Z0 = s[0];
        g_partial[(size_t)(NH - 1) * NB + b] = fabsf(Z0.x - Z0.y);
    }
}

__global__ void reduce_amp_kernel() {
    int k = blockIdx.x * blockDim.x + threadIdx.x;
    if (k >= NBINS) return;
    const float4* p = (const float4*)&g_partial[(size_t)k * NB];
    float acc = 0.f;
    #pragma unroll 8
    for (int i = 0; i < NB / 4; i++) {
        float4 v = p[i];
        acc += v.x + v.y + v.z + v.w;
    }
    g_amp[k] = acc * (1.f / (float)NB);
}

// ---------------------------------------------------------------------------
// 2) prep: weight packs + single-pass top-2 + per-period meta (S = inner+2)
// ---------------------------------------------------------------------------
struct Top2 { float v1; int i1; float v2; int i2; };

__device__ __forceinline__ bool t2gt(float av, int ai, float bv, int bi) {
    return av > bv || (av == bv && ai < bi);
}
__device__ __forceinline__ Top2 t2merge(Top2 a, Top2 b) {
    Top2 r;
    if (t2gt(a.v1, a.i1, b.v1, b.i1)) {
        r.v1 = a.v1; r.i1 = a.i1;
        if (t2gt(a.v2, a.i2, b.v1, b.i1)) { r.v2 = a.v2; r.i2 = a.i2; }
        else                              { r.v2 = b.v1; r.i2 = b.i1; }
    } else {
        r.v1 = b.v1; r.i1 = b.i1;
        if (t2gt(b.v2, b.i2, a.v1, a.i1)) { r.v2 = b.v2; r.i2 = b.i2; }
        else                              { r.v2 = a.v1; r.i2 = a.i1; }
    }
    return r;
}

__global__ void prep_kernel(const float* __restrict__ w1,
                            const float* __restrict__ w2,
                            const float* __restrict__ b1) {
    __shared__ Top2 warpRes[32];
    int tid = threadIdx.x;   // 1024

    const int NP = DMOD / 2;
    for (int idx = tid; idx < 2 * 2 * NP * 9; idx += 1024) {
        int orient = idx / (2 * NP * 9);
        int rem    = idx - orient * 2 * NP * 9;
        int layer  = rem / (NP * 9);
        int i      = rem - layer * NP * 9;
        int p = i / 9, s = i - p * 9;
        int g = s / 3, di = s % 3 - 1;
        int do_ = (g == 0) ? 0 : (g == 1 ? 1 : -1);
        int off = orient ? ((do_ + 1) * 3 + (di + 1)) : ((di + 1) * 3 + (do_ + 1));
        const float* w = layer ? w2 : w1;
        g_wq[orient][layer][i] = make_float2(w[(2 * p) * 9 + off], w[(2 * p + 1) * 9 + off]);
    }
    if (tid < NP) g_b1q[tid] = make_float2(b1[2 * tid], b1[2 * tid + 1]);

    Top2 t;
    t.v1 = g_amp[tid]; t.i1 = tid; t.v2 = -1e30f; t.i2 = 0x7FFFFFFF;
    #pragma unroll
    for (int off = 16; off >= 1; off >>= 1) {
        Top2 o;
        o.v1 = __shfl_xor_sync(0xFFFFFFFFu, t.v1, off);
        o.i1 = __shfl_xor_sync(0xFFFFFFFFu, t.i1, off);
        o.v2 = __shfl_xor_sync(0xFFFFFFFFu, t.v2, off);
        o.i2 = __shfl_xor_sync(0xFFFFFFFFu, t.i2, off);
        t = t2merge(t, o);
    }
    if ((tid & 31) == 0) warpRes[tid >> 5] = t;
    __syncthreads();

    if (tid < 32) {
        t = warpRes[tid];
        #pragma unroll
        for (int off = 16; off >= 1; off >>= 1) {
            Top2 o;
            o.v1 = __shfl_xor_sync(0xFFFFFFFFu, t.v1, off);
            o.i1 = __shfl_xor_sync(0xFFFFFFFFu, t.i1, off);
            o.v2 = __shfl_xor_sync(0xFFFFFFFFu, t.v2, off);
            o.i2 = __shfl_xor_sync(0xFFFFFFFFu, t.i2, off);
            t = t2merge(t, o);
        }
        if (tid == 0) {
            float e2 = __expf(t.v2 - t.v1);
            float inv = 1.f / (1.f + e2);
            float wgts[2] = { inv, e2 * inv };
            int   idxs[2] = { t.i1, t.i2 };
            for (int tt = 0; tt < 2; tt++) {
                int f = idxs[tt] + 1;
                int P = (int)llrint((double)T_LEN / (double)f); if (P < 1) P = 1;
                int cols = (T_LEN + P - 1) / P;
                int orient = (P <= cols) ? 0 : 1;
                int inner = orient ? cols : P;
                int outer = orient ? P : cols;
                // swap so inner = min side (see conv): orient==0 -> inner=P
                inner = orient ? cols : P;
                outer = orient ? P : cols;
                int S = inner + 2;              // no align4: scalar access only
                PMeta pm;
                pm.S = S; pm.padL = outer * S;
                pm.inner = inner; pm.outer = outer;
                pm.stepO = orient ? 1 : P;
                pm.stepI = orient ? P : 1;
                pm.orient = orient;
                pm.magic = 0xFFFFFFFFu / (unsigned)S + 1u;
                pm.wgt = wgts[tt];
                g_pm[tt] = pm;
            }
        }
    }
}

__device__ __forceinline__ ull gelu2(ull vq, ull C0, ull C1, ull HALF) {
    ull v2q = mul2(vq, vq);
    ull uq  = mul2(vq, fma2(C1, v2q, C0));
    float ul, uh;
    unpack2(uq, ul, uh);
    float tl, th;
    asm("tanh.approx.f32 %0, %1;" : "=f"(tl) : "f"(ul));
    asm("tanh.approx.f32 %0, %1;" : "=f"(th) : "f"(uh));
    ull tq = pack2(tl, th);
    return mul2(vq, fma2(HALF, tq, HALF));
}

// ---------------------------------------------------------------------------
// 3) f32x2 channel-paired register-resident fused conv (single-chain, R13)
// ---------------------------------------------------------------------------
__global__ __launch_bounds__(256, 2) void conv_kernel(
        const float* __restrict__ x,
        const float* __restrict__ b2) {
    const int period = blockIdx.z;
    const PMeta pm = g_pm[period];
    const int S = pm.S, inner = pm.inner, padL = pm.padL;
    const int stepO = pm.stepO, stepI = pm.stepI;
    const unsigned M = pm.magic;

    if (blockIdx.x * OUTSPAN >= padL) return;
    const int qb  = blockIdx.x * OUTSPAN - 48;
    const int b   = blockIdx.y;
    const int tid = threadIdx.x;

    __shared__ float xs[XLEN2];
    __shared__ float sUm[USPAN];
    __shared__ float sUp[USPAN];
    __shared__ __align__(16) ull w1s[(DMOD/2) * 9];
    __shared__ __align__(16) ull w2s[(DMOD/2) * 9];
    __shared__ ull b1s[DMOD / 2];
    __shared__ float b2s_s;

    {
        const ull* gw1 = (const ull*)g_wq[pm.orient][0];
        const ull* gw2 = (const ull*)g_wq[pm.orient][1];
        for (int i = tid; i < (DMOD/2) * 9; i += 256) {
            w1s[i] = gw1[i];
            w2s[i] = gw2[i];
        }
        if (tid < DMOD / 2) b1s[tid] = ((const ull*)g_b1q)[tid];
        if (tid == 0) b2s_s = b2[0];
    }

    const float* xb = x + (size_t)b * T_LEN;
    for (int i = tid; i < XLEN2; i += 256) {
        int q = qb - 52 + i;
        float v = 0.f;
        if (q >= 0 && q < padL) {
            unsigned o = mdiv((unsigned)q, M);
            int i_ = q - (int)o * S - 1;
            if (i_ >= 0 && i_ < inner) {
                int n = (int)o * stepO + i_ * stepI;
                if (n < T_LEN) v = xb[n];
            }
        }
        xs[i] = v;
    }
    __syncthreads();

    ull T0[8], T1[8], T2[8];
    {
        const float* xr = xs + tid * 4 + 50;
        #pragma unroll
        for (int k = 0; k < 8; k++) {
            T1[k] = bcast2(xr[k]);
            T2[k] = bcast2(xr[S + k]);
            T0[k] = bcast2(xr[-S + k]);
        }
    }

    ull Mq[6];
    #pragma unroll
    for (int t = 0; t < 6; t++) {
        int q = qb + tid * 4 - 1 + t;
        bool v = false;
        if (q >= 0 && q < padL) {
            unsigned o = mdiv((unsigned)q, M);
            int i_ = q - (int)o * S - 1;
            v = (i_ >= 0 && i_ < inner);
        }
        Mq[t] = bcast2(v ? 1.f : 0.f);
    }
    int on[4]; bool ov[4]; bool anyv = false;
    #pragma unroll
    for (int r = 0; r < 4; r++) {
        int lj = tid * 4 + r;
        int q  = qb + lj;
        ov[r] = false; on[r] = 0;
        if (lj >= 48 && lj < 48 + OUTSPAN && q < padL) {
            unsigned o = mdiv((unsigned)q, M);
            int i_ = q - (int)o * S - 1;
            if (i_ >= 0 && i_ < inner) {
                int n = (int)o * stepO + i_ * stepI;
                if (n < T_LEN) { ov[r] = true; on[r] = n; anyv = true; }
            }
        }
    }

    const ull C0   = bcast2(0.7978845608f);
    const ull C1   = bcast2(0.035677408136f);
    const ull HALF = bcast2(0.5f);

    ull U0q[4], Upq[4], Umq[4];
    #pragma unroll
    for (int r = 0; r < 4; r++) { U0q[r] = 0ull; Upq[r] = 0ull; Umq[r] = 0ull; }

    for (int pch = 0; pch < DMOD / 2; pch++) {
        const ull* w1r = &w1s[pch * 9];
        const ull* w2r = &w2s[pch * 9];
        ull bq = b1s[pch];
        ull hq[6];
        #pragma unroll
        for (int t = 0; t < 6; t++) {
            ull a = bq;
            a = fma2(w1r[0], T1[t],     a);
            a = fma2(w1r[1], T1[t + 1], a);
            a = fma2(w1r[2], T1[t + 2], a);
            a = fma2(w1r[3], T2[t],     a);
            a = fma2(w1r[4], T2[t + 1], a);
            a = fma2(w1r[5], T2[t + 2], a);
            a = fma2(w1r[6], T0[t],     a);
            a = fma2(w1r[7], T0[t + 1], a);
            a = fma2(w1r[8], T0[t + 2], a);
            hq[t] = mul2(gelu2(a, C0, C1, HALF), Mq[t]);
        }
        #pragma unroll
        for (int r = 0; r < 4; r++) {
            U0q[r] = fma2(w2r[0], hq[r],     U0q[r]);
            U0q[r] = fma2(w2r[1], hq[r + 1], U0q[r]);
            U0q[r] = fma2(w2r[2], hq[r + 2], U0q[r]);
            Upq[r] = fma2(w2r[3], hq[r],     Upq[r]);
            Upq[r] = fma2(w2r[4], hq[r + 1], Upq[r]);
            Upq[r] = fma2(w2r[5], hq[r + 2], Upq[r]);
            Umq[r] = fma2(w2r[6], hq[r],     Umq[r]);
            Umq[r] = fma2(w2r[7], hq[r + 1], Umq[r]);
            Umq[r] = fma2(w2r[8], hq[r + 2], Umq[r]);
        }
    }

    float U0[4], Um[4], Up[4];
    #pragma unroll
    for (int r = 0; r < 4; r++) {
        float lo, hi;
        unpack2(U0q[r], lo, hi); U0[r] = lo + hi;
        unpack2(Upq[r], lo, hi); Up[r] = lo + hi;
        unpack2(Umq[r], lo, hi); Um[r] = lo + hi;
    }
    *(float4*)(sUm + tid * 4) = make_float4(Um[0], Um[1], Um[2], Um[3]);
    *(float4*)(sUp + tid * 4) = make_float4(Up[0], Up[1], Up[2], Up[3]);
    __syncthreads();

    if (anyv) {
        float* yout = g_y2[period] + (size_t)b * T_LEN;
        #pragma unroll
        for (int r = 0; r < 4; r++) {
            if (ov[r]) {
                int lj = tid * 4 + r;
                float val = b2s_s + U0[r] + sUm[lj - S] + sUp[lj + S];
                yout[on[r]] = pm.wgt * val;
            }
        }
    }
}

// ---------------------------------------------------------------------------
// 4) Head GEMM, split-K=8, f32x2 inner
// ---------------------------------------------------------------------------
#define GBM 64
#define GBN 64
#define GBK 32
__global__ __launch_bounds__(256) void head_gemm_kernel(
        const float* __restrict__ hw) {
    __shared__ __align__(16) float As[GBK][GBM];
    __shared__ __align__(16) float Bs[GBK][GBN];
    const int tid = threadIdx.x;
    const int n0 = blockIdx.x * GBN, m0 = blockIdx.y * GBM;
    const int kz = blockIdx.z;
    const int ty = tid / 16, tx = tid % 16;
    const int tm = ty * 4, tn = tx * 4;

    const float* y0 = g_y2[0];
    const float* y1 = g_y2[1];

    ull acc2[4][2];
    #pragma unroll
    for (int i = 0; i < 4; i++) { acc2[i][0] = 0ull; acc2[i][1] = 0ull; }

    const int kbase = kz * KSEG;
    for (int k0 = kbase; k0 < kbase + KSEG; k0 += GBK) {
        #pragma unroll
        for (int i = tid; i < GBM * GBK; i += 256) {
            int m = i / GBK, k = i % GBK;
            size_t off = (size_t)(m0 + m) * T_LEN + k0 + k;
            As[k][m] = y0[off] + y1[off];
        }
        #pragma unroll
        for (int i = tid; i < GBN * GBK; i += 256) {
            int n = i / GBK, k = i % GBK;
            Bs[k][n] = (n0 + n < H_OUT) ? hw[(size_t)(n0 + n) * T_LEN + k0 + k] : 0.f;
        }
        __syncthreads();
        #pragma unroll
        for (int k = 0; k < GBK; k++) {
            float4 a4 = *(const float4*)&As[k][tm];
            float4 b4 = *(const float4*)&Bs[k][tn];
            ull bq0 = pack2(b4.x, b4.y);
            ull bq1 = pack2(b4.z, b4.w);
            float av[4] = {a4.x, a4.y, a4.z, a4.w};
            #pragma unroll
            for (int i = 0; i < 4; i++) {
                ull ai = bcast2(av[i]);
                acc2[i][0] = fma2(ai, bq0, acc2[i][0]);
                acc2[i][1] = fma2(ai, bq1, acc2[i][1]);
            }
        }
        __syncthreads();
    }
    float* outp = g_hp[kz];
    #pragma unroll
    for (int i = 0; i < 4; i++) {
        int m = m0 + tm + i;
        float v0, v1v, v2, v3;
        unpack2(acc2[i][0], v0, v1v);
        unpack2(acc2[i][1], v2, v3);
        float vals[4] = {v0, v1v, v2, v3};
        #pragma unroll
        for (int j = 0; j < 4; j++) {
            int n = n0 + tn + j;
            if (n < H_OUT) outp[(size_t)m * H_OUT + n] = vals[j];
        }
    }
}

__global__ void head_epilogue_kernel(const float* __restrict__ hb,
                                     float* __restrict__ out) {
    int idx4 = blockIdx.x * blockDim.x + threadIdx.x;
    if (idx4 >= NB * H_OUT / 4) return;
    int base = idx4 * 4;
    int n = base % H_OUT;
    float4 v = *(const float4*)&hb[n];
    #pragma unroll
    for (int kz = 0; kz < KSPLIT; kz++) {
        float4 p = *(const float4*)&g_hp[kz][base];
        v.x += p.x; v.y += p.y; v.z += p.z; v.w += p.w;
    }
    *(float4*)&out[base] = v;
}

// ---------------------------------------------------------------------------
extern "C" void kernel_launch(void* const* d_in, const int* in_sizes, int n_in,
                              void* d_out, int out_size) {
    const float* x  = (const float*)d_in[0];
    const float* w1 = (const float*)d_in[1];
    const float* b1 = (const float*)d_in[2];
    const float* w2 = (const float*)d_in[3];
    const float* b2 = (const float*)d_in[4];
    const float* hw = (const float*)d_in[5];
    const float* hb = (const float*)d_in[6];
    float* out = (float*)d_out;

    fft_kernel<<<NB, 512>>>(x);
    reduce_amp_kernel<<<NBINS / 256, 256>>>();
    prep_kernel<<<1, NBINS>>>(w1, w2, b1);
    conv_kernel<<<dim3(NCONVBLK, NB, 2), 256>>>(x, b2);
    head_gemm_kernel<<<dim3((H_OUT + GBN - 1) / GBN, NB / GBM, KSPLIT), 256>>>(hw);
    head_epilogue_kernel<<<(NB * H_OUT / 4 + 255) / 256, 256>>>(hb, out);
}